// round 14
// baseline (speedup 1.0000x reference)
#include <cuda_runtime.h>
#include <math.h>
#include <stdint.h>

#define T 1024
#define H 1024
#define NH 8
#define NKV 4
#define HD 128
#define NE 32
#define MI 512
#define SI 1024

// ---------------- scratch ----------------
__device__ float g_h1[T*H];
__device__ float g_qkv[T*2048];
__device__ float g_at[T*H];
__device__ float g_h2[T*H];
__device__ float g_xb[T*H];
__device__ float g_logits[T*NE];
__device__ float g_topkw[T*4];
__device__ int   g_cnt[NE];
__device__ int   g_list[NE*T];
__device__ float g_egu[4096*1024];      // expert up out; also O-proj split-K partials (pre-fork)
__device__ float g_act[4096*512];       // MoE act; attn partial O earlier (disjoint in time)
__device__ float g_edb[4096*1024];
__device__ float g_sgu[T*2048];
__device__ float g_act2[T*SI];
__device__ float g_sdp[2*T*H];          // shared-down split-K partials (chain B private)
__device__ float g_pm[2*T*NH];
__device__ float g_pl[2*T*NH];

// ---------------- asm helpers ----------------
__device__ __forceinline__ void cp16(uint32_t d, const void* s) {
    asm volatile("cp.async.cg.shared.global [%0], [%1], 16;" :: "r"(d), "l"(s));
}
__device__ __forceinline__ void cp_commit() {
    asm volatile("cp.async.commit_group;" ::: "memory");
}
__device__ __forceinline__ void cp_wait1() {
    asm volatile("cp.async.wait_group 1;" ::: "memory");
}
__device__ __forceinline__ void cp_wait0() {
    asm volatile("cp.async.wait_group 0;" ::: "memory");
}

// ---------------- fp32 GEMM: 128x128 tile, 8x8 microtile ----------------
struct Bseg { const float* p[4]; int base[4]; };

#define TS_F 4608
#define GEMM_SMEM (TS_F * 4 * 4)

template <bool BNT, bool GATHER, bool KSPLIT>
__global__ __launch_bounds__(256, 2)
void fgemm(const float* __restrict__ A, int lda, Bseg Bs, int ldb, size_t estride,
           float* __restrict__ C, int ldc, size_t zstride, int K,
           const int* __restrict__ cnt, const int* __restrict__ list, int shift) {
    extern __shared__ __align__(16) float smemf[];
    __shared__ int rows_s[128];
    const int tid = threadIdx.x;
    const int tx = tid & 15, ty = tid >> 4;
    const int n0 = blockIdx.x * 128;
    const int m0 = blockIdx.y * 128;
    int e = 0, kbase = 0;
    if (GATHER) e = blockIdx.z;
    if (KSPLIT) { kbase = blockIdx.z * K; C += (size_t)blockIdx.z * zstride; }

    if (GATHER) {
        int me = cnt[e];
        if (m0 >= me) return;
        if (tid < 128) rows_s[tid] = (m0 + tid < me) ? list[e * T + m0 + tid] : -1;
        __syncthreads();
    }
    const int sgi = n0 >> 9;
    const float* Bp = Bs.p[sgi] + (size_t)e * estride;
    const int nb0 = n0 - Bs.base[sgi];
    const uint32_t sb = (uint32_t)__cvta_generic_to_shared(smemf);

    auto load_stage = [&](int cc, int slot) {
        const int k0 = kbase + cc * 32;
        const uint32_t sA = sb + slot * (TS_F * 4);
        const uint32_t sB = sb + (2 * TS_F + slot * TS_F) * 4;
#pragma unroll
        for (int it = 0; it < 4; it++) {
            int idx = tid + it * 256;
            int r = idx >> 3, ch = idx & 7;
            size_t arow;
            if (GATHER) { int j = rows_s[r]; arow = (j < 0) ? 0 : (size_t)(j >> shift); }
            else arow = (size_t)(m0 + r);
            cp16(sA + r * 144 + ch * 16, A + arow * lda + k0 + ch * 4);
            if (BNT) {
                cp16(sB + r * 144 + ch * 16, Bp + (size_t)(nb0 + r) * ldb + k0 + ch * 4);
            } else {
                int kr = idx >> 5, nc = idx & 31;
                cp16(sB + kr * 528 + nc * 16, Bp + (size_t)(k0 + kr) * ldb + nb0 + nc * 4);
            }
        }
    };

    float acc[8][8];
#pragma unroll
    for (int i = 0; i < 8; i++)
#pragma unroll
        for (int j = 0; j < 8; j++) acc[i][j] = 0.f;

    const int nch = K >> 5;
    load_stage(0, 0); cp_commit();
    load_stage(1, 1); cp_commit();

    for (int c = 0; c < nch; c++) {
        if (c + 2 < nch) cp_wait1(); else cp_wait0();
        __syncthreads();
        const int slot = c & 1;
        const float* Ab = smemf + slot * TS_F;
        const float* Bb = smemf + (2 + slot) * TS_F;
#pragma unroll 1
        for (int kq = 0; kq < 8; kq++) {
            float a_[8][4];
#pragma unroll
            for (int i = 0; i < 8; i++) {
                float4 f = *(const float4*)&Ab[(ty * 8 + i) * 36 + kq * 4];
                a_[i][0] = f.x; a_[i][1] = f.y; a_[i][2] = f.z; a_[i][3] = f.w;
            }
            if (BNT) {
#pragma unroll
                for (int jh = 0; jh < 2; jh++) {
                    float4 b4[4];
#pragma unroll
                    for (int j4 = 0; j4 < 4; j4++)
                        b4[j4] = *(const float4*)&Bb[((jh * 4 + j4) * 16 + tx) * 36 + kq * 4];
#pragma unroll
                    for (int i = 0; i < 8; i++)
#pragma unroll
                        for (int j4 = 0; j4 < 4; j4++) {
                            float v = acc[i][jh * 4 + j4];
                            v = fmaf(a_[i][0], b4[j4].x, v);
                            v = fmaf(a_[i][1], b4[j4].y, v);
                            v = fmaf(a_[i][2], b4[j4].z, v);
                            v = fmaf(a_[i][3], b4[j4].w, v);
                            acc[i][jh * 4 + j4] = v;
                        }
                }
            } else {
#pragma unroll
                for (int kk = 0; kk < 4; kk++) {
                    float4 b0 = *(const float4*)&Bb[(kq * 4 + kk) * 132 + tx * 4];
                    float4 b1 = *(const float4*)&Bb[(kq * 4 + kk) * 132 + 64 + tx * 4];
#pragma unroll
                    for (int i = 0; i < 8; i++) {
                        float av = a_[i][kk];
                        acc[i][0] = fmaf(av, b0.x, acc[i][0]);
                        acc[i][1] = fmaf(av, b0.y, acc[i][1]);
                        acc[i][2] = fmaf(av, b0.z, acc[i][2]);
                        acc[i][3] = fmaf(av, b0.w, acc[i][3]);
                        acc[i][4] = fmaf(av, b1.x, acc[i][4]);
                        acc[i][5] = fmaf(av, b1.y, acc[i][5]);
                        acc[i][6] = fmaf(av, b1.z, acc[i][6]);
                        acc[i][7] = fmaf(av, b1.w, acc[i][7]);
                    }
                }
            }
        }
        __syncthreads();
        if (c + 2 < nch) { load_stage(c + 2, slot); cp_commit(); }
    }

    // epilogue
#pragma unroll
    for (int i = 0; i < 8; i++) {
        int lr = ty * 8 + i;
        float* crow;
        if (GATHER) {
            int jj = rows_s[lr];
            if (jj < 0) continue;
            crow = C + (size_t)jj * ldc;
        } else {
            crow = C + (size_t)(m0 + lr) * ldc;
        }
        if (BNT) {
#pragma unroll
            for (int j = 0; j < 8; j++)
                crow[n0 + j * 16 + tx] = acc[i][j];
        } else {
#pragma unroll
            for (int jh = 0; jh < 2; jh++)
                *(float4*)&crow[n0 + jh * 64 + tx * 4] =
                    make_float4(acc[i][jh*4+0], acc[i][jh*4+1], acc[i][jh*4+2], acc[i][jh*4+3]);
        }
    }
}

// ---------------- split-KV flash attention ----------------
#define ATT_SMEM ((4224 + 8448 + 8448 + 2176) * 4)

__global__ __launch_bounds__(256, 2)
void attn_kernel(const float* __restrict__ qkv, float* __restrict__ po,
                 float* __restrict__ pm, float* __restrict__ pl) {
    extern __shared__ __align__(16) float sm[];
    float* Qs = sm;
    float* Ks = sm + 4224;
    float* Vs = sm + 12672;
    float* Ps = sm + 21120;
    const int h = blockIdx.x;
    const int y = blockIdx.y;
    const int qt = (y < 32) ? (31 - y) : (63 - y);
    const int c  = (y < 32) ? 0 : 1;
    const int ntile = (qt >> 1) + 1;
    const int kt0 = c ? 8 : 0;
    const int kt1 = c ? ntile : min(8, ntile);
    const int kvh = h >> 1;
    const int tid = threadIdx.x;
    const int tx = tid & 15, ty = tid >> 4;
    const uint32_t sb = (uint32_t)__cvta_generic_to_shared(sm);

#pragma unroll
    for (int it = 0; it < 4; it++) {
        int idx = tid + it * 256;
        int r = idx >> 5, cc = idx & 31;
        cp16(sb + (r * 132 + cc * 4) * 4,
             qkv + (size_t)(qt * 32 + r) * 2048 + h * 128 + cc * 4);
    }
    cp_commit();

    float m_[2] = {-1e30f, -1e30f}, l_[2] = {0.f, 0.f};
    float o_[2][8];
#pragma unroll
    for (int i = 0; i < 2; i++)
#pragma unroll
        for (int j = 0; j < 8; j++) o_[i][j] = 0.f;

    const float scale = 0.088388347648318447f;
    const int qg0 = qt * 32 + ty * 2;

    for (int kt = kt0; kt < kt1; kt++) {
        __syncthreads();
#pragma unroll
        for (int it = 0; it < 8; it++) {
            int idx = tid + it * 256;
            int r = idx >> 5, cc = idx & 31;
            cp16(sb + (4224 + r * 132 + cc * 4) * 4,
                 qkv + (size_t)(kt * 64 + r) * 2048 + 1024 + kvh * 128 + cc * 4);
        }
#pragma unroll
        for (int it = 0; it < 8; it++) {
            int idx = tid + it * 256;
            int r = idx >> 5, cc = idx & 31;
            cp16(sb + (12672 + r * 132 + cc * 4) * 4,
                 qkv + (size_t)(kt * 64 + r) * 2048 + 1536 + kvh * 128 + cc * 4);
        }
        cp_commit();
        cp_wait0();
        __syncthreads();

        float s[2][4];
#pragma unroll
        for (int i = 0; i < 2; i++)
#pragma unroll
            for (int j = 0; j < 4; j++) s[i][j] = 0.f;
#pragma unroll 8
        for (int d4 = 0; d4 < 32; d4++) {
            float4 a0 = *(const float4*)&Qs[(ty * 2 + 0) * 132 + d4 * 4];
            float4 a1 = *(const float4*)&Qs[(ty * 2 + 1) * 132 + d4 * 4];
#pragma unroll
            for (int j = 0; j < 4; j++) {
                float4 b = *(const float4*)&Ks[(j * 16 + tx) * 132 + d4 * 4];
                s[0][j] = fmaf(a0.x, b.x, fmaf(a0.y, b.y, fmaf(a0.z, b.z, fmaf(a0.w, b.w, s[0][j]))));
                s[1][j] = fmaf(a1.x, b.x, fmaf(a1.y, b.y, fmaf(a1.z, b.z, fmaf(a1.w, b.w, s[1][j]))));
            }
        }
#pragma unroll
        for (int i = 0; i < 2; i++)
#pragma unroll
            for (int j = 0; j < 4; j++) {
                int kg = kt * 64 + j * 16 + tx;
                s[i][j] = (kg <= qg0 + i) ? s[i][j] * scale : -1e30f;
            }
#pragma unroll
        for (int i = 0; i < 2; i++) {
            float mt = fmaxf(fmaxf(s[i][0], s[i][1]), fmaxf(s[i][2], s[i][3]));
            mt = fmaxf(mt, __shfl_xor_sync(0xffffffffu, mt, 8));
            mt = fmaxf(mt, __shfl_xor_sync(0xffffffffu, mt, 4));
            mt = fmaxf(mt, __shfl_xor_sync(0xffffffffu, mt, 2));
            mt = fmaxf(mt, __shfl_xor_sync(0xffffffffu, mt, 1));
            float mn = fmaxf(m_[i], mt);
            float corr = __expf(m_[i] - mn);
            float p0 = __expf(s[i][0] - mn), p1 = __expf(s[i][1] - mn);
            float p2 = __expf(s[i][2] - mn), p3 = __expf(s[i][3] - mn);
            float rs = p0 + p1 + p2 + p3;
            rs += __shfl_xor_sync(0xffffffffu, rs, 8);
            rs += __shfl_xor_sync(0xffffffffu, rs, 4);
            rs += __shfl_xor_sync(0xffffffffu, rs, 2);
            rs += __shfl_xor_sync(0xffffffffu, rs, 1);
            l_[i] = l_[i] * corr + rs;
            m_[i] = mn;
#pragma unroll
            for (int jj = 0; jj < 8; jj++) o_[i][jj] *= corr;
            int prow = (ty * 2 + i) * 68;
            Ps[prow + tx]      = p0;
            Ps[prow + 16 + tx] = p1;
            Ps[prow + 32 + tx] = p2;
            Ps[prow + 48 + tx] = p3;
        }
        __syncthreads();
#pragma unroll 4
        for (int k = 0; k < 64; k++) {
            float p0 = Ps[(ty * 2 + 0) * 68 + k];
            float p1 = Ps[(ty * 2 + 1) * 68 + k];
            float4 v0 = *(const float4*)&Vs[k * 132 + tx * 4];
            float4 v1 = *(const float4*)&Vs[k * 132 + 64 + tx * 4];
            o_[0][0] = fmaf(p0, v0.x, o_[0][0]); o_[0][1] = fmaf(p0, v0.y, o_[0][1]);
            o_[0][2] = fmaf(p0, v0.z, o_[0][2]); o_[0][3] = fmaf(p0, v0.w, o_[0][3]);
            o_[0][4] = fmaf(p0, v1.x, o_[0][4]); o_[0][5] = fmaf(p0, v1.y, o_[0][5]);
            o_[0][6] = fmaf(p0, v1.z, o_[0][6]); o_[0][7] = fmaf(p0, v1.w, o_[0][7]);
            o_[1][0] = fmaf(p1, v0.x, o_[1][0]); o_[1][1] = fmaf(p1, v0.y, o_[1][1]);
            o_[1][2] = fmaf(p1, v0.z, o_[1][2]); o_[1][3] = fmaf(p1, v0.w, o_[1][3]);
            o_[1][4] = fmaf(p1, v1.x, o_[1][4]); o_[1][5] = fmaf(p1, v1.y, o_[1][5]);
            o_[1][6] = fmaf(p1, v1.z, o_[1][6]); o_[1][7] = fmaf(p1, v1.w, o_[1][7]);
        }
    }
#pragma unroll
    for (int i = 0; i < 2; i++) {
        int row = qt * 32 + ty * 2 + i;
        size_t base = (size_t)c * ((size_t)T * H) + (size_t)row * H + h * 128;
        *(float4*)&po[base + tx * 4] =
            make_float4(o_[i][0], o_[i][1], o_[i][2], o_[i][3]);
        *(float4*)&po[base + 64 + tx * 4] =
            make_float4(o_[i][4], o_[i][5], o_[i][6], o_[i][7]);
        if (tx == 0) {
            pm[c * (T * NH) + row * NH + h] = m_[i];
            pl[c * (T * NH) + row * NH + h] = l_[i];
        }
    }
}

__global__ void attn_combine(const float* __restrict__ po, const float* __restrict__ pm,
                             const float* __restrict__ pl, float* __restrict__ out) {
    int idx = blockIdx.x * blockDim.x + threadIdx.x;
    if (idx >= T * H) return;
    int q = idx >> 10;
    int h = (idx & 1023) >> 7;
    int qt = q >> 5;
    float m0 = pm[q * NH + h], l0 = pl[q * NH + h];
    float o0 = po[idx];
    if (qt >= 16) {
        float m1 = pm[T * NH + q * NH + h], l1 = pl[T * NH + q * NH + h];
        float o1 = po[(size_t)T * H + idx];
        float mm = fmaxf(m0, m1);
        float e0 = __expf(m0 - mm), e1 = __expf(m1 - mm);
        out[idx] = (o0 * e0 + o1 * e1) / (l0 * e0 + l1 * e1);
    } else {
        out[idx] = o0 / l0;
    }
}

// ---------------- elementwise / norms ----------------
__global__ void rmsnorm_kernel(const float* __restrict__ x, const float* __restrict__ w,
                               float* __restrict__ out) {
    int t = blockIdx.x;
    const float* xr = x + (size_t)t * H;
    float s = 0.f;
    for (int i = threadIdx.x; i < H; i += blockDim.x) { float v = xr[i]; s += v * v; }
    __shared__ float red[32];
    for (int o = 16; o; o >>= 1) s += __shfl_xor_sync(0xffffffffu, s, o);
    if ((threadIdx.x & 31) == 0) red[threadIdx.x >> 5] = s;
    __syncthreads();
    if (threadIdx.x < 32) {
        float v = (threadIdx.x < (blockDim.x >> 5)) ? red[threadIdx.x] : 0.f;
        for (int o = 16; o; o >>= 1) v += __shfl_xor_sync(0xffffffffu, v, o);
        if (threadIdx.x == 0) red[0] = v;
    }
    __syncthreads();
    float inv = rsqrtf(red[0] * (1.f / H) + 1e-6f);
    for (int i = threadIdx.x; i < H; i += blockDim.x)
        out[(size_t)t * H + i] = xr[i] * inv * w[i];
}

__global__ void add_rmsnorm_kernel(const float* __restrict__ a, const float* __restrict__ b,
                                   const float* __restrict__ c, const float* __restrict__ w,
                                   float* __restrict__ h2, float* __restrict__ xb) {
    int t = blockIdx.x;
    size_t base = (size_t)t * H;
    float s = 0.f;
    for (int i = threadIdx.x; i < H; i += blockDim.x) {
        float v = a[base + i] + b[base + i] + c[base + i];
        h2[base + i] = v;
        s += v * v;
    }
    __shared__ float red[32];
    for (int o = 16; o; o >>= 1) s += __shfl_xor_sync(0xffffffffu, s, o);
    if ((threadIdx.x & 31) == 0) red[threadIdx.x >> 5] = s;
    __syncthreads();
    if (threadIdx.x < 32) {
        float v = (threadIdx.x < (blockDim.x >> 5)) ? red[threadIdx.x] : 0.f;
        for (int o = 16; o; o >>= 1) v += __shfl_xor_sync(0xffffffffu, v, o);
        if (threadIdx.x == 0) red[0] = v;
    }
    __syncthreads();
    float inv = rsqrtf(red[0] * (1.f / H) + 1e-6f);
    for (int i = threadIdx.x; i < H; i += blockDim.x)
        xb[base + i] = h2[base + i] * inv * w[i];
}

__global__ void silu_pair_kernel(const float* __restrict__ x, float* __restrict__ o,
                                 int total, int w, int ldx) {
    int idx = blockIdx.x * blockDim.x + threadIdx.x;
    if (idx >= total) return;
    int r = idx / w, c = idx - r * w;
    float g = x[(size_t)r * ldx + c];
    float u = x[(size_t)r * ldx + w + c];
    o[idx] = g / (1.f + __expf(-g)) * u;
}

__global__ void zero_cnt_kernel(int* cnt) { if (threadIdx.x < NE) cnt[threadIdx.x] = 0; }

__global__ void rope_kernel(float* __restrict__ qkv, const int* __restrict__ pos) {
    int t = blockIdx.x;
    int i = threadIdx.x;
    int hh = threadIdx.y;
    float p = (float)pos[t];
    float inv = exp2f(-(float)i * (13.287712379549449f / 64.f));
    float sv, cv;
    sincosf(p * inv, &sv, &cv);
    float* base = (hh < 8) ? (qkv + (size_t)t * 2048 + hh * HD)
                           : (qkv + (size_t)t * 2048 + 1024 + (hh - 8) * HD);
    float x1 = base[i], x2 = base[i + 64];
    base[i]      = x1 * cv - x2 * sv;
    base[i + 64] = x2 * cv + x1 * sv;
}

// ---------------- router ----------------
__global__ void router_gemm(const float* __restrict__ xb, const float* __restrict__ rw,
                            float* __restrict__ logits) {
    __shared__ float xr[H];
    int t = blockIdx.x;
    for (int i = threadIdx.x; i < H; i += 128) xr[i] = xb[(size_t)t * H + i];
    __syncthreads();
    int w = threadIdx.x >> 5, lane = threadIdx.x & 31;
    for (int e8 = 0; e8 < 8; e8++) {
        int e = w * 8 + e8;
        const float* wr = rw + (size_t)e * H;
        float s = 0.f;
        for (int k = lane; k < H; k += 32) s += xr[k] * wr[k];
        for (int o = 16; o; o >>= 1) s += __shfl_xor_sync(0xffffffffu, s, o);
        if (lane == 0) logits[t * NE + e] = s;
    }
}

__global__ void router_kernel(const float* __restrict__ logits, const float* __restrict__ bias,
                              float* __restrict__ topkw, int* __restrict__ cnt,
                              int* __restrict__ list) {
    int t = blockIdx.x * blockDim.x + threadIdx.x;
    if (t >= T) return;
    float sc[NE], sfc[NE];
#pragma unroll
    for (int e = 0; e < NE; e++) {
        float l = logits[t * NE + e];
        float s = 1.f / (1.f + __expf(-l));
        sc[e] = s; sfc[e] = s + bias[e];
    }
    float gs[8];
#pragma unroll
    for (int g = 0; g < 8; g++) {
        float v[4] = {sfc[g*4+0], sfc[g*4+1], sfc[g*4+2], sfc[g*4+3]};
        float sum = v[0] + v[1] + v[2] + v[3];
        int mi = 0;
        for (int i = 1; i < 4; i++) if (v[i] < v[mi]) mi = i;
        float m2 = 1e30f;
        for (int i = 0; i < 4; i++) if (i != mi && v[i] < m2) m2 = v[i];
        gs[g] = sum - v[mi] - m2;
    }
    bool gsel[8] = {};
    for (int r = 0; r < 4; r++) {
        float best = -1e30f; int bi = 0;
        for (int g = 0; g < 8; g++) if (!gsel[g] && gs[g] > best) { best = gs[g]; bi = g; }
        gsel[bi] = true;
    }
    float masked[NE];
#pragma unroll
    for (int e = 0; e < NE; e++) masked[e] = gsel[e >> 2] ? sfc[e] : 0.f;
    int idxs[4]; float ws[4]; float wsum = 0.f;
    for (int r = 0; r < 4; r++) {
        float best = -1e30f; int bi = 0;
        for (int e = 0; e < NE; e++) if (masked[e] > best) { best = masked[e]; bi = e; }
        masked[bi] = -1e30f;
        idxs[r] = bi; ws[r] = sc[bi]; wsum += ws[r];
    }
    float inv = 2.5f / (wsum + 1e-20f);
    for (int r = 0; r < 4; r++) {
        topkw[t * 4 + r] = ws[r] * inv;
        int pos = atomicAdd(&cnt[idxs[r]], 1);
        list[idxs[r] * T + pos] = t * 4 + r;
    }
}

// final: out = h2 + shared_down(p0+p1) + sum_k tw*ed
__global__ void final_kernel(const float* __restrict__ h2, const float* __restrict__ p0,
                             const float* __restrict__ p1, const float* __restrict__ ed,
                             const float* __restrict__ tw, float* __restrict__ out) {
    int idx = blockIdx.x * blockDim.x + threadIdx.x;
    if (idx >= T * H) return;
    int t = idx >> 10;
    int hh = idx & 1023;
    float r = h2[idx] + p0[idx] + p1[idx];
#pragma unroll
    for (int kk = 0; kk < 4; kk++)
        r += tw[t * 4 + kk] * ed[(size_t)(t * 4 + kk) * H + hh];
    out[idx] = r;
}

// ---------------- host ----------------
extern "C" void kernel_launch(void* const* d_in, const int* in_sizes, int n_in,
                              void* d_out, int out_size) {
    (void)in_sizes; (void)n_in; (void)out_size;
    const float* hidden   = (const float*)d_in[0];
    const int*   pos      = (const int*)d_in[1];
    const float* ln1_w    = (const float*)d_in[2];
    const float* ln2_w    = (const float*)d_in[3];
    const float* q_w      = (const float*)d_in[4];
    const float* k_w      = (const float*)d_in[5];
    const float* v_w      = (const float*)d_in[6];
    const float* o_w      = (const float*)d_in[7];
    const float* router_w = (const float*)d_in[8];
    const float* r_bias   = (const float*)d_in[9];
    const float* eg_w     = (const float*)d_in[10];
    const float* eu_w     = (const float*)d_in[11];
    const float* ed_w     = (const float*)d_in[12];
    const float* sg_w     = (const float*)d_in[13];
    const float* su_w     = (const float*)d_in[14];
    const float* sd_w     = (const float*)d_in[15];
    float* out = (float*)d_out;

#define GSYM(p, s) cudaGetSymbolAddress((void**)&p, s)
    float *h1, *qkv, *at, *h2, *xb, *logits, *topkw, *egu, *act, *edb, *sgu, *act2, *sdp, *pm, *pl;
    int *cnt, *list;
    GSYM(h1,g_h1); GSYM(qkv,g_qkv); GSYM(at,g_at); GSYM(h2,g_h2); GSYM(xb,g_xb);
    GSYM(logits,g_logits); GSYM(topkw,g_topkw); GSYM(cnt,g_cnt); GSYM(list,g_list);
    GSYM(egu,g_egu); GSYM(act,g_act); GSYM(edb,g_edb);
    GSYM(sgu,g_sgu); GSYM(act2,g_act2); GSYM(sdp,g_sdp); GSYM(pm,g_pm); GSYM(pl,g_pl);
#undef GSYM
    float* part0 = egu;                      // O-proj partials (pre-fork only)
    float* part1 = egu + (size_t)T * H;
    float* po = act;                         // attn partial O (pre-MoE only)
    float* sdp0 = sdp;                       // shared-down partials (chain B)
    float* sdp1 = sdp + (size_t)T * H;

    // one-time stream/event setup (correctness call; reused under capture)
    static cudaStream_t s1 = nullptr;
    static cudaEvent_t evFork = nullptr, evJoin = nullptr;
    if (!s1) {
        cudaStreamCreateWithFlags(&s1, cudaStreamNonBlocking);
        cudaEventCreateWithFlags(&evFork, cudaEventDisableTiming);
        cudaEventCreateWithFlags(&evJoin, cudaEventDisableTiming);
    }

    cudaFuncSetAttribute(fgemm<true,false,false>,  cudaFuncAttributeMaxDynamicSharedMemorySize, GEMM_SMEM);
    cudaFuncSetAttribute(fgemm<true,false,true>,   cudaFuncAttributeMaxDynamicSharedMemorySize, GEMM_SMEM);
    cudaFuncSetAttribute(fgemm<false,false,false>, cudaFuncAttributeMaxDynamicSharedMemorySize, GEMM_SMEM);
    cudaFuncSetAttribute(fgemm<false,false,true>,  cudaFuncAttributeMaxDynamicSharedMemorySize, GEMM_SMEM);
    cudaFuncSetAttribute(fgemm<false,true,false>,  cudaFuncAttributeMaxDynamicSharedMemorySize, GEMM_SMEM);
    cudaFuncSetAttribute(attn_kernel, cudaFuncAttributeMaxDynamicSharedMemorySize, ATT_SMEM);
    cudaFuncSetAttribute(attn_kernel, cudaFuncAttributePreferredSharedMemoryCarveout, 100);

    // ---- serial head (stream 0); attn at my launch #4 for ncu ----
    rmsnorm_kernel<<<T, 256>>>(hidden, ln1_w, h1);                          // 1
    {   // 2: fused QKV GEMM (NT)
        Bseg b = {{q_w, q_w, k_w, v_w}, {0, 0, 1024, 1536}};
        fgemm<true,false,false><<<dim3(16, 8), 256, GEMM_SMEM>>>(
            h1, 1024, b, 1024, 0, qkv, 2048, 0, 1024, nullptr, nullptr, 0);
    }
    rope_kernel<<<T, dim3(64, 12)>>>(qkv, pos);                             // 3
    attn_kernel<<<dim3(NH, 48), 256, ATT_SMEM>>>(qkv, po, pm, pl);          // 4 <-- PROFILED
    attn_combine<<<(T * H + 255) / 256, 256>>>(po, pm, pl, at);             // 5
    {   // O projection (NT), split-K=2
        Bseg b = {{o_w, o_w, o_w, o_w}, {0, 0, 0, 0}};
        fgemm<true,false,true><<<dim3(8, 8, 2), 256, GEMM_SMEM>>>(
            at, 1024, b, 1024, 0, part0, 1024, (size_t)T * H, 512, nullptr, nullptr, 0);
    }
    zero_cnt_kernel<<<1, 32>>>(cnt);
    add_rmsnorm_kernel<<<T, 256>>>(hidden, part0, part1, ln2_w, h2, xb);

    // ---- fork: chain B (shared expert) on s1 ----
    cudaEventRecord(evFork, 0);
    cudaStreamWaitEvent(s1, evFork, 0);
    {   // shared expert up: fused sg|su (NN)
        Bseg b = {{sg_w, sg_w, su_w, su_w}, {0, 0, 1024, 1024}};
        fgemm<false,false,false><<<dim3(16, 8), 256, GEMM_SMEM, s1>>>(
            xb, 1024, b, 1024, 0, sgu, 2048, 0, 1024, nullptr, nullptr, 0);
    }
    silu_pair_kernel<<<(T * SI + 255) / 256, 256, 0, s1>>>(sgu, act2, T * SI, 1024, 2048);
    {   // shared down (NN), split-K=2 -> sdp partials
        Bseg b = {{sd_w, sd_w, sd_w, sd_w}, {0, 0, 0, 0}};
        fgemm<false,false,true><<<dim3(8, 8, 2), 256, GEMM_SMEM, s1>>>(
            act2, 1024, b, 1024, 0, sdp0, 1024, (size_t)T * H, 512, nullptr, nullptr, 0);
    }
    cudaEventRecord(evJoin, s1);

    // ---- chain A (routed experts) on stream 0, concurrent with chain B ----
    router_gemm<<<T, 128>>>(xb, router_w, logits);
    router_kernel<<<(T + 255) / 256, 256>>>(logits, r_bias, topkw, cnt, list);
    {   // routed experts up: fused eg|eu (NN + gather)
        Bseg b = {{eg_w, eu_w, eg_w, eu_w}, {0, 512, 0, 512}};
        fgemm<false,true,false><<<dim3(8, 8, NE), 256, GEMM_SMEM>>>(
            xb, 1024, b, 512, (size_t)1024*512, egu, 1024, 0, 1024, cnt, list, 2);
    }
    silu_pair_kernel<<<(4096 * 512 + 255) / 256, 256>>>(egu, act, 4096 * 512, 512, 1024);
    {   // expert down (NN + gather)
        Bseg b = {{ed_w, ed_w, ed_w, ed_w}, {0, 0, 0, 0}};
        fgemm<false,true,false><<<dim3(8, 8, NE), 256, GEMM_SMEM>>>(
            act, 512, b, 1024, (size_t)512*1024, edb, 1024, 0, 512, cnt, list, 0);
    }

    // ---- join + final combine ----
    cudaStreamWaitEvent(0, evJoin, 0);
    final_kernel<<<(T * H + 255) / 256, 256>>>(h2, sdp0, sdp1, edb, topkw, out);
}

// round 15
// speedup vs baseline: 1.5554x; 1.5554x over previous
#include <cuda_runtime.h>
#include <math.h>
#include <stdint.h>

#define T 1024
#define H 1024
#define NH 8
#define NKV 4
#define HD 128
#define NE 32
#define MI 512
#define SI 1024

// ---------------- scratch ----------------
__device__ float g_h1[T*H];
__device__ float g_qkv[T*2048];
__device__ float g_at[T*H];
__device__ float g_h2[T*H];
__device__ float g_xb[T*H];
__device__ float g_logits[T*NE];
__device__ float g_topkw[T*4];
__device__ int   g_cnt[NE];
__device__ int   g_list[NE*T];
__device__ float g_egu[4096*1024];      // expert up out; also O-proj split-K partials (earlier)
__device__ float g_act[4096*512];       // expert act; attn partial O earlier (disjoint in time)
__device__ float g_edb[4096*1024];
__device__ float g_sgu[T*2048];
__device__ float g_act2[T*SI];
__device__ float g_sdp[2*T*H];          // shared-down split-K partials
__device__ float g_pm[2*T*NH];
__device__ float g_pl[2*T*NH];

// ---------------- asm helpers ----------------
__device__ __forceinline__ void cp16(uint32_t d, const void* s) {
    asm volatile("cp.async.cg.shared.global [%0], [%1], 16;" :: "r"(d), "l"(s));
}
__device__ __forceinline__ void cp_commit() {
    asm volatile("cp.async.commit_group;" ::: "memory");
}
__device__ __forceinline__ void cp_wait1() {
    asm volatile("cp.async.wait_group 1;" ::: "memory");
}
__device__ __forceinline__ void cp_wait0() {
    asm volatile("cp.async.wait_group 0;" ::: "memory");
}

// ---------------- fp32 GEMM (NT, attention projections) ----------------
struct Bseg { const float* p[4]; int base[4]; };

#define TS_F 4608
#define GEMM_SMEM (TS_F * 4 * 4)

template <bool KSPLIT>
__global__ __launch_bounds__(256, 2)
void fgemm_nt(const float* __restrict__ A, int lda, Bseg Bs, int ldb,
              float* __restrict__ C, int ldc, size_t zstride, int K) {
    extern __shared__ __align__(16) float smemf[];
    const int tid = threadIdx.x;
    const int tx = tid & 15, ty = tid >> 4;
    const int n0 = blockIdx.x * 128;
    const int m0 = blockIdx.y * 128;
    int kbase = 0;
    if (KSPLIT) { kbase = blockIdx.z * K; C += (size_t)blockIdx.z * zstride; }

    const int sgi = n0 >> 9;
    const float* Bp = Bs.p[sgi];
    const int nb0 = n0 - Bs.base[sgi];
    const uint32_t sb = (uint32_t)__cvta_generic_to_shared(smemf);

    auto load_stage = [&](int cc, int slot) {
        const int k0 = kbase + cc * 32;
        const uint32_t sA = sb + slot * (TS_F * 4);
        const uint32_t sB = sb + (2 * TS_F + slot * TS_F) * 4;
#pragma unroll
        for (int it = 0; it < 4; it++) {
            int idx = tid + it * 256;
            int r = idx >> 3, ch = idx & 7;
            cp16(sA + r * 144 + ch * 16, A + (size_t)(m0 + r) * lda + k0 + ch * 4);
            cp16(sB + r * 144 + ch * 16, Bp + (size_t)(nb0 + r) * ldb + k0 + ch * 4);
        }
    };

    float acc[8][8];
#pragma unroll
    for (int i = 0; i < 8; i++)
#pragma unroll
        for (int j = 0; j < 8; j++) acc[i][j] = 0.f;

    const int nch = K >> 5;
    load_stage(0, 0); cp_commit();
    load_stage(1, 1); cp_commit();

    for (int c = 0; c < nch; c++) {
        if (c + 2 < nch) cp_wait1(); else cp_wait0();
        __syncthreads();
        const int slot = c & 1;
        const float* Ab = smemf + slot * TS_F;
        const float* Bb = smemf + (2 + slot) * TS_F;
#pragma unroll 1
        for (int kq = 0; kq < 8; kq++) {
            float a_[8][4];
#pragma unroll
            for (int i = 0; i < 8; i++) {
                float4 f = *(const float4*)&Ab[(ty * 8 + i) * 36 + kq * 4];
                a_[i][0] = f.x; a_[i][1] = f.y; a_[i][2] = f.z; a_[i][3] = f.w;
            }
#pragma unroll
            for (int jh = 0; jh < 2; jh++) {
                float4 b4[4];
#pragma unroll
                for (int j4 = 0; j4 < 4; j4++)
                    b4[j4] = *(const float4*)&Bb[((jh * 4 + j4) * 16 + tx) * 36 + kq * 4];
#pragma unroll
                for (int i = 0; i < 8; i++)
#pragma unroll
                    for (int j4 = 0; j4 < 4; j4++) {
                        float v = acc[i][jh * 4 + j4];
                        v = fmaf(a_[i][0], b4[j4].x, v);
                        v = fmaf(a_[i][1], b4[j4].y, v);
                        v = fmaf(a_[i][2], b4[j4].z, v);
                        v = fmaf(a_[i][3], b4[j4].w, v);
                        acc[i][jh * 4 + j4] = v;
                    }
            }
        }
        __syncthreads();
        if (c + 2 < nch) { load_stage(c + 2, slot); cp_commit(); }
    }

#pragma unroll
    for (int i = 0; i < 8; i++) {
        float* crow = C + (size_t)(m0 + ty * 8 + i) * ldc;
#pragma unroll
        for (int j = 0; j < 8; j++)
            crow[n0 + j * 16 + tx] = acc[i][j];
    }
}

// ---------------- merged MoE GEMM: experts (gather) + shared (dense) in one grid ----------------
// z in [0,32): gather expert tile. z = 32,33: dense shared tile.
// UP:   gather: egu[j] += xb[j>>2] @ eg|eu[e]   (K=1024, ldb=512, N=1024 fused g|u)
//       dense z-32=s: sgu[t][s*1024 + n] = xb[t] @ (s? su : sg)  (K=1024)
// DOWN: gather: edb[j] = act[j] @ ed[e]          (K=512)
//       dense z-32=s: sdp[s][t][n] = act2[t][kset s] @ sd[kset s]  (split-K)
template <bool UP>
__global__ __launch_bounds__(256, 2)
void moe_gemm(const float* __restrict__ Ag, const float* __restrict__ Bg0,
              const float* __restrict__ Bg1, float* __restrict__ Cg,
              const float* __restrict__ Ad, const float* __restrict__ Bd0,
              const float* __restrict__ Bd1, float* __restrict__ Cd,
              const int* __restrict__ cnt, const int* __restrict__ list) {
    extern __shared__ __align__(16) float smemf[];
    __shared__ int rows_s[128];
    const int tid = threadIdx.x;
    const int tx = tid & 15, ty = tid >> 4;
    const int n0 = blockIdx.x * 128;
    const int m0 = blockIdx.y * 128;
    const int z = blockIdx.z;
    const bool gather = (z < 32);
    const int zz = z - 32;

    const float* A; const float* Bp; float* C;
    int lda, ldb, ldc, K, kb, nb0;
    const int shift = UP ? 2 : 0;
    if (gather) {
        int me = cnt[z];
        if (m0 >= me) return;
        if (tid < 128) rows_s[tid] = (m0 + tid < me) ? list[z * T + m0 + tid] : -1;
        __syncthreads();
        A = Ag; lda = UP ? 1024 : 512; K = UP ? 1024 : 512; kb = 0;
        if (UP) {
            int sgi = n0 >> 9;
            Bp = (sgi ? Bg1 : Bg0) + (size_t)z * (1024 * 512);
            nb0 = n0 - sgi * 512; ldb = 512;
        } else {
            Bp = Bg0 + (size_t)z * (512 * 1024);
            nb0 = n0; ldb = 1024;
        }
        C = Cg; ldc = 1024;
    } else {
        A = Ad; lda = 1024;
        if (UP) {
            K = 1024; kb = 0;
            Bp = zz ? Bd1 : Bd0; nb0 = n0; ldb = 1024;
            C = Cd + zz * 1024; ldc = 2048;
        } else {
            K = 512; kb = zz * 512;
            Bp = Bd0; nb0 = n0; ldb = 1024;
            C = Cd + (size_t)zz * ((size_t)T * H); ldc = 1024;
        }
    }
    const uint32_t sb = (uint32_t)__cvta_generic_to_shared(smemf);

    auto load_stage = [&](int cc, int slot) {
        const int k0 = kb + cc * 32;
        const uint32_t sA = sb + slot * (TS_F * 4);
        const uint32_t sB = sb + (2 * TS_F + slot * TS_F) * 4;
#pragma unroll
        for (int it = 0; it < 4; it++) {
            int idx = tid + it * 256;
            int r = idx >> 3, ch = idx & 7;
            size_t arow;
            if (gather) { int j = rows_s[r]; arow = (j < 0) ? 0 : (size_t)(j >> shift); }
            else arow = (size_t)(m0 + r);
            cp16(sA + r * 144 + ch * 16, A + arow * lda + k0 + ch * 4);
            int kr = idx >> 5, nc = idx & 31;
            cp16(sB + kr * 528 + nc * 16, Bp + (size_t)(k0 + kr) * ldb + nb0 + nc * 4);
        }
    };

    float acc[8][8];
#pragma unroll
    for (int i = 0; i < 8; i++)
#pragma unroll
        for (int j = 0; j < 8; j++) acc[i][j] = 0.f;

    const int nch = K >> 5;
    load_stage(0, 0); cp_commit();
    load_stage(1, 1); cp_commit();

    for (int c = 0; c < nch; c++) {
        if (c + 2 < nch) cp_wait1(); else cp_wait0();
        __syncthreads();
        const int slot = c & 1;
        const float* Ab = smemf + slot * TS_F;
        const float* Bb = smemf + (2 + slot) * TS_F;
#pragma unroll 1
        for (int kq = 0; kq < 8; kq++) {
            float a_[8][4];
#pragma unroll
            for (int i = 0; i < 8; i++) {
                float4 f = *(const float4*)&Ab[(ty * 8 + i) * 36 + kq * 4];
                a_[i][0] = f.x; a_[i][1] = f.y; a_[i][2] = f.z; a_[i][3] = f.w;
            }
#pragma unroll
            for (int kk = 0; kk < 4; kk++) {
                float4 b0 = *(const float4*)&Bb[(kq * 4 + kk) * 132 + tx * 4];
                float4 b1 = *(const float4*)&Bb[(kq * 4 + kk) * 132 + 64 + tx * 4];
#pragma unroll
                for (int i = 0; i < 8; i++) {
                    float av = a_[i][kk];
                    acc[i][0] = fmaf(av, b0.x, acc[i][0]);
                    acc[i][1] = fmaf(av, b0.y, acc[i][1]);
                    acc[i][2] = fmaf(av, b0.z, acc[i][2]);
                    acc[i][3] = fmaf(av, b0.w, acc[i][3]);
                    acc[i][4] = fmaf(av, b1.x, acc[i][4]);
                    acc[i][5] = fmaf(av, b1.y, acc[i][5]);
                    acc[i][6] = fmaf(av, b1.z, acc[i][6]);
                    acc[i][7] = fmaf(av, b1.w, acc[i][7]);
                }
            }
        }
        __syncthreads();
        if (c + 2 < nch) { load_stage(c + 2, slot); cp_commit(); }
    }

#pragma unroll
    for (int i = 0; i < 8; i++) {
        int lr = ty * 8 + i;
        float* crow;
        if (gather) {
            int jj = rows_s[lr];
            if (jj < 0) continue;
            crow = C + (size_t)jj * ldc;
        } else {
            crow = C + (size_t)(m0 + lr) * ldc;
        }
#pragma unroll
        for (int jh = 0; jh < 2; jh++)
            *(float4*)&crow[n0 + jh * 64 + tx * 4] =
                make_float4(acc[i][jh*4+0], acc[i][jh*4+1], acc[i][jh*4+2], acc[i][jh*4+3]);
    }
}

// ---------------- split-KV flash attention ----------------
#define ATT_SMEM ((4224 + 8448 + 8448 + 2176) * 4)

__global__ __launch_bounds__(256, 2)
void attn_kernel(const float* __restrict__ qkv, float* __restrict__ po,
                 float* __restrict__ pm, float* __restrict__ pl) {
    extern __shared__ __align__(16) float sm[];
    float* Qs = sm;
    float* Ks = sm + 4224;
    float* Vs = sm + 12672;
    float* Ps = sm + 21120;
    const int h = blockIdx.x;
    const int y = blockIdx.y;
    const int qt = (y < 32) ? (31 - y) : (63 - y);
    const int c  = (y < 32) ? 0 : 1;
    const int ntile = (qt >> 1) + 1;
    const int kt0 = c ? 8 : 0;
    const int kt1 = c ? ntile : min(8, ntile);
    const int kvh = h >> 1;
    const int tid = threadIdx.x;
    const int tx = tid & 15, ty = tid >> 4;
    const uint32_t sb = (uint32_t)__cvta_generic_to_shared(sm);

#pragma unroll
    for (int it = 0; it < 4; it++) {
        int idx = tid + it * 256;
        int r = idx >> 5, cc = idx & 31;
        cp16(sb + (r * 132 + cc * 4) * 4,
             qkv + (size_t)(qt * 32 + r) * 2048 + h * 128 + cc * 4);
    }
    cp_commit();

    float m_[2] = {-1e30f, -1e30f}, l_[2] = {0.f, 0.f};
    float o_[2][8];
#pragma unroll
    for (int i = 0; i < 2; i++)
#pragma unroll
        for (int j = 0; j < 8; j++) o_[i][j] = 0.f;

    const float scale = 0.088388347648318447f;
    const int qg0 = qt * 32 + ty * 2;

    for (int kt = kt0; kt < kt1; kt++) {
        __syncthreads();
#pragma unroll
        for (int it = 0; it < 8; it++) {
            int idx = tid + it * 256;
            int r = idx >> 5, cc = idx & 31;
            cp16(sb + (4224 + r * 132 + cc * 4) * 4,
                 qkv + (size_t)(kt * 64 + r) * 2048 + 1024 + kvh * 128 + cc * 4);
        }
#pragma unroll
        for (int it = 0; it < 8; it++) {
            int idx = tid + it * 256;
            int r = idx >> 5, cc = idx & 31;
            cp16(sb + (12672 + r * 132 + cc * 4) * 4,
                 qkv + (size_t)(kt * 64 + r) * 2048 + 1536 + kvh * 128 + cc * 4);
        }
        cp_commit();
        cp_wait0();
        __syncthreads();

        float s[2][4];
#pragma unroll
        for (int i = 0; i < 2; i++)
#pragma unroll
            for (int j = 0; j < 4; j++) s[i][j] = 0.f;
#pragma unroll 8
        for (int d4 = 0; d4 < 32; d4++) {
            float4 a0 = *(const float4*)&Qs[(ty * 2 + 0) * 132 + d4 * 4];
            float4 a1 = *(const float4*)&Qs[(ty * 2 + 1) * 132 + d4 * 4];
#pragma unroll
            for (int j = 0; j < 4; j++) {
                float4 b = *(const float4*)&Ks[(j * 16 + tx) * 132 + d4 * 4];
                s[0][j] = fmaf(a0.x, b.x, fmaf(a0.y, b.y, fmaf(a0.z, b.z, fmaf(a0.w, b.w, s[0][j]))));
                s[1][j] = fmaf(a1.x, b.x, fmaf(a1.y, b.y, fmaf(a1.z, b.z, fmaf(a1.w, b.w, s[1][j]))));
            }
        }
#pragma unroll
        for (int i = 0; i < 2; i++)
#pragma unroll
            for (int j = 0; j < 4; j++) {
                int kg = kt * 64 + j * 16 + tx;
                s[i][j] = (kg <= qg0 + i) ? s[i][j] * scale : -1e30f;
            }
#pragma unroll
        for (int i = 0; i < 2; i++) {
            float mt = fmaxf(fmaxf(s[i][0], s[i][1]), fmaxf(s[i][2], s[i][3]));
            mt = fmaxf(mt, __shfl_xor_sync(0xffffffffu, mt, 8));
            mt = fmaxf(mt, __shfl_xor_sync(0xffffffffu, mt, 4));
            mt = fmaxf(mt, __shfl_xor_sync(0xffffffffu, mt, 2));
            mt = fmaxf(mt, __shfl_xor_sync(0xffffffffu, mt, 1));
            float mn = fmaxf(m_[i], mt);
            float corr = __expf(m_[i] - mn);
            float p0 = __expf(s[i][0] - mn), p1 = __expf(s[i][1] - mn);
            float p2 = __expf(s[i][2] - mn), p3 = __expf(s[i][3] - mn);
            float rs = p0 + p1 + p2 + p3;
            rs += __shfl_xor_sync(0xffffffffu, rs, 8);
            rs += __shfl_xor_sync(0xffffffffu, rs, 4);
            rs += __shfl_xor_sync(0xffffffffu, rs, 2);
            rs += __shfl_xor_sync(0xffffffffu, rs, 1);
            l_[i] = l_[i] * corr + rs;
            m_[i] = mn;
#pragma unroll
            for (int jj = 0; jj < 8; jj++) o_[i][jj] *= corr;
            int prow = (ty * 2 + i) * 68;
            Ps[prow + tx]      = p0;
            Ps[prow + 16 + tx] = p1;
            Ps[prow + 32 + tx] = p2;
            Ps[prow + 48 + tx] = p3;
        }
        __syncthreads();
#pragma unroll 4
        for (int k = 0; k < 64; k++) {
            float p0 = Ps[(ty * 2 + 0) * 68 + k];
            float p1 = Ps[(ty * 2 + 1) * 68 + k];
            float4 v0 = *(const float4*)&Vs[k * 132 + tx * 4];
            float4 v1 = *(const float4*)&Vs[k * 132 + 64 + tx * 4];
            o_[0][0] = fmaf(p0, v0.x, o_[0][0]); o_[0][1] = fmaf(p0, v0.y, o_[0][1]);
            o_[0][2] = fmaf(p0, v0.z, o_[0][2]); o_[0][3] = fmaf(p0, v0.w, o_[0][3]);
            o_[0][4] = fmaf(p0, v1.x, o_[0][4]); o_[0][5] = fmaf(p0, v1.y, o_[0][5]);
            o_[0][6] = fmaf(p0, v1.z, o_[0][6]); o_[0][7] = fmaf(p0, v1.w, o_[0][7]);
            o_[1][0] = fmaf(p1, v0.x, o_[1][0]); o_[1][1] = fmaf(p1, v0.y, o_[1][1]);
            o_[1][2] = fmaf(p1, v0.z, o_[1][2]); o_[1][3] = fmaf(p1, v0.w, o_[1][3]);
            o_[1][4] = fmaf(p1, v1.x, o_[1][4]); o_[1][5] = fmaf(p1, v1.y, o_[1][5]);
            o_[1][6] = fmaf(p1, v1.z, o_[1][6]); o_[1][7] = fmaf(p1, v1.w, o_[1][7]);
        }
    }
#pragma unroll
    for (int i = 0; i < 2; i++) {
        int row = qt * 32 + ty * 2 + i;
        size_t base = (size_t)c * ((size_t)T * H) + (size_t)row * H + h * 128;
        *(float4*)&po[base + tx * 4] =
            make_float4(o_[i][0], o_[i][1], o_[i][2], o_[i][3]);
        *(float4*)&po[base + 64 + tx * 4] =
            make_float4(o_[i][4], o_[i][5], o_[i][6], o_[i][7]);
        if (tx == 0) {
            pm[c * (T * NH) + row * NH + h] = m_[i];
            pl[c * (T * NH) + row * NH + h] = l_[i];
        }
    }
}

__global__ void attn_combine(const float* __restrict__ po, const float* __restrict__ pm,
                             const float* __restrict__ pl, float* __restrict__ out) {
    int idx = blockIdx.x * blockDim.x + threadIdx.x;
    if (idx >= T * H) return;
    int q = idx >> 10;
    int h = (idx & 1023) >> 7;
    int qt = q >> 5;
    float m0 = pm[q * NH + h], l0 = pl[q * NH + h];
    float o0 = po[idx];
    if (qt >= 16) {
        float m1 = pm[T * NH + q * NH + h], l1 = pl[T * NH + q * NH + h];
        float o1 = po[(size_t)T * H + idx];
        float mm = fmaxf(m0, m1);
        float e0 = __expf(m0 - mm), e1 = __expf(m1 - mm);
        out[idx] = (o0 * e0 + o1 * e1) / (l0 * e0 + l1 * e1);
    } else {
        out[idx] = o0 / l0;
    }
}

// ---------------- elementwise / norms ----------------
__global__ void rmsnorm_kernel(const float* __restrict__ x, const float* __restrict__ w,
                               float* __restrict__ out) {
    int t = blockIdx.x;
    const float* xr = x + (size_t)t * H;
    float s = 0.f;
    for (int i = threadIdx.x; i < H; i += blockDim.x) { float v = xr[i]; s += v * v; }
    __shared__ float red[32];
    for (int o = 16; o; o >>= 1) s += __shfl_xor_sync(0xffffffffu, s, o);
    if ((threadIdx.x & 31) == 0) red[threadIdx.x >> 5] = s;
    __syncthreads();
    if (threadIdx.x < 32) {
        float v = (threadIdx.x < (blockDim.x >> 5)) ? red[threadIdx.x] : 0.f;
        for (int o = 16; o; o >>= 1) v += __shfl_xor_sync(0xffffffffu, v, o);
        if (threadIdx.x == 0) red[0] = v;
    }
    __syncthreads();
    float inv = rsqrtf(red[0] * (1.f / H) + 1e-6f);
    for (int i = threadIdx.x; i < H; i += blockDim.x)
        out[(size_t)t * H + i] = xr[i] * inv * w[i];
}

__global__ void add_rmsnorm_kernel(const float* __restrict__ a, const float* __restrict__ b,
                                   const float* __restrict__ c, const float* __restrict__ w,
                                   float* __restrict__ h2, float* __restrict__ xb) {
    int t = blockIdx.x;
    size_t base = (size_t)t * H;
    float s = 0.f;
    for (int i = threadIdx.x; i < H; i += blockDim.x) {
        float v = a[base + i] + b[base + i] + c[base + i];
        h2[base + i] = v;
        s += v * v;
    }
    __shared__ float red[32];
    for (int o = 16; o; o >>= 1) s += __shfl_xor_sync(0xffffffffu, s, o);
    if ((threadIdx.x & 31) == 0) red[threadIdx.x >> 5] = s;
    __syncthreads();
    if (threadIdx.x < 32) {
        float v = (threadIdx.x < (blockDim.x >> 5)) ? red[threadIdx.x] : 0.f;
        for (int o = 16; o; o >>= 1) v += __shfl_xor_sync(0xffffffffu, v, o);
        if (threadIdx.x == 0) red[0] = v;
    }
    __syncthreads();
    float inv = rsqrtf(red[0] * (1.f / H) + 1e-6f);
    for (int i = threadIdx.x; i < H; i += blockDim.x)
        xb[base + i] = h2[base + i] * inv * w[i];
}

// fused silu for both chains: [0, 2M) expert (egu->act), [2M, 3M) shared (sgu->act2)
__global__ void silu_both_kernel(const float* __restrict__ egu, float* __restrict__ act,
                                 const float* __restrict__ sgu, float* __restrict__ act2) {
    int idx = blockIdx.x * blockDim.x + threadIdx.x;
    if (idx < 4096 * 512) {
        int r = idx >> 9, c = idx & 511;
        float g = egu[(size_t)r * 1024 + c];
        float u = egu[(size_t)r * 1024 + 512 + c];
        act[idx] = g / (1.f + __expf(-g)) * u;
    } else {
        int j = idx - 4096 * 512;
        if (j >= T * SI) return;
        int r = j >> 10, c = j & 1023;
        float g = sgu[(size_t)r * 2048 + c];
        float u = sgu[(size_t)r * 2048 + 1024 + c];
        act2[j] = g / (1.f + __expf(-g)) * u;
    }
}

__global__ void zero_cnt_kernel(int* cnt) { if (threadIdx.x < NE) cnt[threadIdx.x] = 0; }

__global__ void rope_kernel(float* __restrict__ qkv, const int* __restrict__ pos) {
    int t = blockIdx.x;
    int i = threadIdx.x;
    int hh = threadIdx.y;
    float p = (float)pos[t];
    float inv = exp2f(-(float)i * (13.287712379549449f / 64.f));
    float sv, cv;
    sincosf(p * inv, &sv, &cv);
    float* base = (hh < 8) ? (qkv + (size_t)t * 2048 + hh * HD)
                           : (qkv + (size_t)t * 2048 + 1024 + (hh - 8) * HD);
    float x1 = base[i], x2 = base[i + 64];
    base[i]      = x1 * cv - x2 * sv;
    base[i + 64] = x2 * cv + x1 * sv;
}

// ---------------- router ----------------
__global__ void router_gemm(const float* __restrict__ xb, const float* __restrict__ rw,
                            float* __restrict__ logits) {
    __shared__ float xr[H];
    int t = blockIdx.x;
    for (int i = threadIdx.x; i < H; i += 128) xr[i] = xb[(size_t)t * H + i];
    __syncthreads();
    int w = threadIdx.x >> 5, lane = threadIdx.x & 31;
    for (int e8 = 0; e8 < 8; e8++) {
        int e = w * 8 + e8;
        const float* wr = rw + (size_t)e * H;
        float s = 0.f;
        for (int k = lane; k < H; k += 32) s += xr[k] * wr[k];
        for (int o = 16; o; o >>= 1) s += __shfl_xor_sync(0xffffffffu, s, o);
        if (lane == 0) logits[t * NE + e] = s;
    }
}

__global__ void router_kernel(const float* __restrict__ logits, const float* __restrict__ bias,
                              float* __restrict__ topkw, int* __restrict__ cnt,
                              int* __restrict__ list) {
    int t = blockIdx.x * blockDim.x + threadIdx.x;
    if (t >= T) return;
    float sc[NE], sfc[NE];
#pragma unroll
    for (int e = 0; e < NE; e++) {
        float l = logits[t * NE + e];
        float s = 1.f / (1.f + __expf(-l));
        sc[e] = s; sfc[e] = s + bias[e];
    }
    float gs[8];
#pragma unroll
    for (int g = 0; g < 8; g++) {
        float v[4] = {sfc[g*4+0], sfc[g*4+1], sfc[g*4+2], sfc[g*4+3]};
        float sum = v[0] + v[1] + v[2] + v[3];
        int mi = 0;
        for (int i = 1; i < 4; i++) if (v[i] < v[mi]) mi = i;
        float m2 = 1e30f;
        for (int i = 0; i < 4; i++) if (i != mi && v[i] < m2) m2 = v[i];
        gs[g] = sum - v[mi] - m2;
    }
    bool gsel[8] = {};
    for (int r = 0; r < 4; r++) {
        float best = -1e30f; int bi = 0;
        for (int g = 0; g < 8; g++) if (!gsel[g] && gs[g] > best) { best = gs[g]; bi = g; }
        gsel[bi] = true;
    }
    float masked[NE];
#pragma unroll
    for (int e = 0; e < NE; e++) masked[e] = gsel[e >> 2] ? sfc[e] : 0.f;
    int idxs[4]; float ws[4]; float wsum = 0.f;
    for (int r = 0; r < 4; r++) {
        float best = -1e30f; int bi = 0;
        for (int e = 0; e < NE; e++) if (masked[e] > best) { best = masked[e]; bi = e; }
        masked[bi] = -1e30f;
        idxs[r] = bi; ws[r] = sc[bi]; wsum += ws[r];
    }
    float inv = 2.5f / (wsum + 1e-20f);
    for (int r = 0; r < 4; r++) {
        topkw[t * 4 + r] = ws[r] * inv;
        int pos = atomicAdd(&cnt[idxs[r]], 1);
        list[idxs[r] * T + pos] = t * 4 + r;
    }
}

// final: out = h2 + shared_down(p0+p1) + sum_k tw*ed
__global__ void final_kernel(const float* __restrict__ h2, const float* __restrict__ p0,
                             const float* __restrict__ p1, const float* __restrict__ ed,
                             const float* __restrict__ tw, float* __restrict__ out) {
    int idx = blockIdx.x * blockDim.x + threadIdx.x;
    if (idx >= T * H) return;
    int t = idx >> 10;
    int hh = idx & 1023;
    float r = h2[idx] + p0[idx] + p1[idx];
#pragma unroll
    for (int kk = 0; kk < 4; kk++)
        r += tw[t * 4 + kk] * ed[(size_t)(t * 4 + kk) * H + hh];
    out[idx] = r;
}

// ---------------- host ----------------
extern "C" void kernel_launch(void* const* d_in, const int* in_sizes, int n_in,
                              void* d_out, int out_size) {
    (void)in_sizes; (void)n_in; (void)out_size;
    const float* hidden   = (const float*)d_in[0];
    const int*   pos      = (const int*)d_in[1];
    const float* ln1_w    = (const float*)d_in[2];
    const float* ln2_w    = (const float*)d_in[3];
    const float* q_w      = (const float*)d_in[4];
    const float* k_w      = (const float*)d_in[5];
    const float* v_w      = (const float*)d_in[6];
    const float* o_w      = (const float*)d_in[7];
    const float* router_w = (const float*)d_in[8];
    const float* r_bias   = (const float*)d_in[9];
    const float* eg_w     = (const float*)d_in[10];
    const float* eu_w     = (const float*)d_in[11];
    const float* ed_w     = (const float*)d_in[12];
    const float* sg_w     = (const float*)d_in[13];
    const float* su_w     = (const float*)d_in[14];
    const float* sd_w     = (const float*)d_in[15];
    float* out = (float*)d_out;

#define GSYM(p, s) cudaGetSymbolAddress((void**)&p, s)
    float *h1, *qkv, *at, *h2, *xb, *logits, *topkw, *egu, *act, *edb, *sgu, *act2, *sdp, *pm, *pl;
    int *cnt, *list;
    GSYM(h1,g_h1); GSYM(qkv,g_qkv); GSYM(at,g_at); GSYM(h2,g_h2); GSYM(xb,g_xb);
    GSYM(logits,g_logits); GSYM(topkw,g_topkw); GSYM(cnt,g_cnt); GSYM(list,g_list);
    GSYM(egu,g_egu); GSYM(act,g_act); GSYM(edb,g_edb);
    GSYM(sgu,g_sgu); GSYM(act2,g_act2); GSYM(sdp,g_sdp); GSYM(pm,g_pm); GSYM(pl,g_pl);
#undef GSYM
    float* part0 = egu;                      // O-proj partials (pre-MoE only)
    float* part1 = egu + (size_t)T * H;
    float* po = act;                         // attn partial O (pre-MoE only)
    float* sdp0 = sdp;
    float* sdp1 = sdp + (size_t)T * H;

    cudaFuncSetAttribute(fgemm_nt<false>, cudaFuncAttributeMaxDynamicSharedMemorySize, GEMM_SMEM);
    cudaFuncSetAttribute(fgemm_nt<true>,  cudaFuncAttributeMaxDynamicSharedMemorySize, GEMM_SMEM);
    cudaFuncSetAttribute(moe_gemm<true>,  cudaFuncAttributeMaxDynamicSharedMemorySize, GEMM_SMEM);
    cudaFuncSetAttribute(moe_gemm<false>, cudaFuncAttributeMaxDynamicSharedMemorySize, GEMM_SMEM);
    cudaFuncSetAttribute(attn_kernel, cudaFuncAttributeMaxDynamicSharedMemorySize, ATT_SMEM);
    cudaFuncSetAttribute(attn_kernel, cudaFuncAttributePreferredSharedMemoryCarveout, 100);

    // ---- attention branch (attn at my launch #4 for ncu) ----
    rmsnorm_kernel<<<T, 256>>>(hidden, ln1_w, h1);                          // 1
    {   // 2: fused QKV GEMM (NT)
        Bseg b = {{q_w, q_w, k_w, v_w}, {0, 0, 1024, 1536}};
        fgemm_nt<false><<<dim3(16, 8), 256, GEMM_SMEM>>>(
            h1, 1024, b, 1024, qkv, 2048, 0, 1024);
    }
    rope_kernel<<<T, dim3(64, 12)>>>(qkv, pos);                             // 3
    attn_kernel<<<dim3(NH, 48), 256, ATT_SMEM>>>(qkv, po, pm, pl);          // 4 <-- PROFILED
    attn_combine<<<(T * H + 255) / 256, 256>>>(po, pm, pl, at);             // 5
    {   // O projection (NT), split-K=2
        Bseg b = {{o_w, o_w, o_w, o_w}, {0, 0, 0, 0}};
        fgemm_nt<true><<<dim3(8, 8, 2), 256, GEMM_SMEM>>>(
            at, 1024, b, 1024, part0, 1024, (size_t)T * H, 512);
    }
    zero_cnt_kernel<<<1, 32>>>(cnt);
    add_rmsnorm_kernel<<<T, 256>>>(hidden, part0, part1, ln2_w, h2, xb);

    // ---- MoE (merged routed + shared, single stream) ----
    router_gemm<<<T, 128>>>(xb, router_w, logits);
    router_kernel<<<(T + 255) / 256, 256>>>(logits, r_bias, topkw, cnt, list);

    // merged UP: z<32 expert gather (eg|eu), z=32/33 shared sg/su
    moe_gemm<true><<<dim3(8, 8, 34), 256, GEMM_SMEM>>>(
        xb, eg_w, eu_w, egu, xb, sg_w, su_w, sgu, cnt, list);

    silu_both_kernel<<<(4096 * 512 + T * SI + 255) / 256, 256>>>(egu, act, sgu, act2);

    // merged DOWN: z<32 expert gather (ed), z=32/33 shared sd split-K halves
    moe_gemm<false><<<dim3(8, 8, 34), 256, GEMM_SMEM>>>(
        act, ed_w, ed_w, edb, act2, sd_w, sd_w, sdp0, cnt, list);

    final_kernel<<<(T * H + 255) / 256, 256>>>(h2, sdp0, sdp1, edb, topkw, out);
}

// round 16
// speedup vs baseline: 1.5843x; 1.0186x over previous
#include <cuda_runtime.h>
#include <math.h>
#include <stdint.h>

#define T 1024
#define H 1024
#define NH 8
#define NKV 4
#define HD 128
#define NE 32
#define MI 512
#define SI 1024

// ---------------- scratch ----------------
__device__ float g_h1[T*H];
__device__ float g_qkv[T*2048];
__device__ float g_at[T*H];
__device__ float g_h2[T*H];
__device__ float g_xb[T*H];
__device__ float g_logits[T*NE];
__device__ float g_topkw[T*4];
__device__ int   g_cnt[NE];
__device__ int   g_list[NE*T];
__device__ float g_part[2*T*H];         // O-proj split-K partials
__device__ float g_act[4096*512];       // expert act; attn partial O earlier (disjoint)
__device__ float g_edb[4096*1024];
__device__ float g_act2[T*SI];
__device__ float g_sdp[2*T*H];          // shared-down split-K partials
__device__ float g_pm[2*T*NH];
__device__ float g_pl[2*T*NH];

// ---------------- asm helpers ----------------
__device__ __forceinline__ void cp16(uint32_t d, const void* s) {
    asm volatile("cp.async.cg.shared.global [%0], [%1], 16;" :: "r"(d), "l"(s));
}
__device__ __forceinline__ void cp_commit() {
    asm volatile("cp.async.commit_group;" ::: "memory");
}
__device__ __forceinline__ void cp_wait1() {
    asm volatile("cp.async.wait_group 1;" ::: "memory");
}
__device__ __forceinline__ void cp_wait0() {
    asm volatile("cp.async.wait_group 0;" ::: "memory");
}

// ---------------- fp32 GEMM cores ----------------
struct Bseg { const float* p[4]; int base[4]; };

#define TS_F 4608
#define GEMM_SMEM (TS_F * 4 * 4)

// NT GEMM (attention projections). ROPE: apply rotary in epilogue using pos
// (q cols [0,1024), k cols [1024,1536), v passthrough).
template <bool KSPLIT, bool ROPE>
__global__ __launch_bounds__(256, 2)
void fgemm_nt(const float* __restrict__ A, int lda, Bseg Bs, int ldb,
              float* __restrict__ C, int ldc, size_t zstride, int K,
              const int* __restrict__ pos) {
    extern __shared__ __align__(16) float smemf[];
    const int tid = threadIdx.x;
    const int tx = tid & 15, ty = tid >> 4;
    const int n0 = blockIdx.x * 128;
    const int m0 = blockIdx.y * 128;
    int kbase = 0;
    if (KSPLIT) { kbase = blockIdx.z * K; C += (size_t)blockIdx.z * zstride; }

    const int sgi = n0 >> 9;
    const float* Bp = Bs.p[sgi];
    const int nb0 = n0 - Bs.base[sgi];
    const uint32_t sb = (uint32_t)__cvta_generic_to_shared(smemf);

    auto load_stage = [&](int cc, int slot) {
        const int k0 = kbase + cc * 32;
        const uint32_t sA = sb + slot * (TS_F * 4);
        const uint32_t sB = sb + (2 * TS_F + slot * TS_F) * 4;
#pragma unroll
        for (int it = 0; it < 4; it++) {
            int idx = tid + it * 256;
            int r = idx >> 3, ch = idx & 7;
            cp16(sA + r * 144 + ch * 16, A + (size_t)(m0 + r) * lda + k0 + ch * 4);
            cp16(sB + r * 144 + ch * 16, Bp + (size_t)(nb0 + r) * ldb + k0 + ch * 4);
        }
    };

    float acc[8][8];
#pragma unroll
    for (int i = 0; i < 8; i++)
#pragma unroll
        for (int j = 0; j < 8; j++) acc[i][j] = 0.f;

    const int nch = K >> 5;
    load_stage(0, 0); cp_commit();
    load_stage(1, 1); cp_commit();

    for (int c = 0; c < nch; c++) {
        if (c + 2 < nch) cp_wait1(); else cp_wait0();
        __syncthreads();
        const int slot = c & 1;
        const float* Ab = smemf + slot * TS_F;
        const float* Bb = smemf + (2 + slot) * TS_F;
#pragma unroll 1
        for (int kq = 0; kq < 8; kq++) {
            float a_[8][4];
#pragma unroll
            for (int i = 0; i < 8; i++) {
                float4 f = *(const float4*)&Ab[(ty * 8 + i) * 36 + kq * 4];
                a_[i][0] = f.x; a_[i][1] = f.y; a_[i][2] = f.z; a_[i][3] = f.w;
            }
#pragma unroll
            for (int jh = 0; jh < 2; jh++) {
                float4 b4[4];
#pragma unroll
                for (int j4 = 0; j4 < 4; j4++)
                    b4[j4] = *(const float4*)&Bb[((jh * 4 + j4) * 16 + tx) * 36 + kq * 4];
#pragma unroll
                for (int i = 0; i < 8; i++)
#pragma unroll
                    for (int j4 = 0; j4 < 4; j4++) {
                        float v = acc[i][jh * 4 + j4];
                        v = fmaf(a_[i][0], b4[j4].x, v);
                        v = fmaf(a_[i][1], b4[j4].y, v);
                        v = fmaf(a_[i][2], b4[j4].z, v);
                        v = fmaf(a_[i][3], b4[j4].w, v);
                        acc[i][jh * 4 + j4] = v;
                    }
            }
        }
        __syncthreads();
        if (c + 2 < nch) { load_stage(c + 2, slot); cp_commit(); }
    }

    const bool do_rope = ROPE && (n0 < 1536);
#pragma unroll
    for (int i = 0; i < 8; i++) {
        int gr = m0 + ty * 8 + i;
        float* crow = C + (size_t)gr * ldc;
        if (do_rope) {
            float p = (float)pos[gr];
#pragma unroll
            for (int j = 0; j < 4; j++) {
                int ch = j * 16 + tx;              // col in head, [0,64)
                float inv = exp2f(-(float)ch * (13.287712379549449f / 64.f));
                float sv, cv;
                sincosf(p * inv, &sv, &cv);
                float x1 = acc[i][j], x2 = acc[i][j + 4];
                crow[n0 + ch]      = x1 * cv - x2 * sv;
                crow[n0 + ch + 64] = x2 * cv + x1 * sv;
            }
        } else {
#pragma unroll
            for (int j = 0; j < 8; j++)
                crow[n0 + j * 16 + tx] = acc[i][j];
        }
    }
}

// ---------------- merged MoE UP with fused SiLU epilogue ----------------
// z in [0,32): expert gather (x<8 active); z=32: shared dense (x<16).
// B tile cols [0,64) = G weights cols [c0,c0+64), cols [64,128) = U weights
// same cols. Epilogue writes act = silu(g)*u directly (64 act cols per tile).
__global__ __launch_bounds__(256, 2)
void moe_up(const float* __restrict__ xb,
            const float* __restrict__ eg, const float* __restrict__ eu,
            const float* __restrict__ sg, const float* __restrict__ su,
            float* __restrict__ act, float* __restrict__ act2,
            const int* __restrict__ cnt, const int* __restrict__ list) {
    extern __shared__ __align__(16) float smemf[];
    __shared__ int rows_s[128];
    const int tid = threadIdx.x;
    const int tx = tid & 15, ty = tid >> 4;
    const int m0 = blockIdx.y * 128;
    const int z = blockIdx.z;
    const bool gather = (z < 32);

    const float *Bg, *Bu;
    float* Cp;
    int ldb, ldc, c0;
    if (gather) {
        if (blockIdx.x >= 8) return;               // act cols = 512 -> 8 tiles
        int me = cnt[z];
        if (m0 >= me) return;
        if (tid < 128) rows_s[tid] = (m0 + tid < me) ? list[z * T + m0 + tid] : -1;
        __syncthreads();
        Bg = eg + (size_t)z * (1024 * 512);
        Bu = eu + (size_t)z * (1024 * 512);
        ldb = 512; Cp = act; ldc = 512;
        c0 = blockIdx.x * 64;
    } else {
        Bg = sg; Bu = su; ldb = 1024;
        Cp = act2; ldc = 1024;
        c0 = blockIdx.x * 64;                      // x < 16
    }
    const uint32_t sb = (uint32_t)__cvta_generic_to_shared(smemf);

    auto load_stage = [&](int cc, int slot) {
        const int k0 = cc * 32;
        const uint32_t sA = sb + slot * (TS_F * 4);
        const uint32_t sB = sb + (2 * TS_F + slot * TS_F) * 4;
#pragma unroll
        for (int it = 0; it < 4; it++) {
            int idx = tid + it * 256;
            int r = idx >> 3, ch = idx & 7;
            size_t arow;
            if (gather) { int j = rows_s[r]; arow = (j < 0) ? 0 : (size_t)(j >> 2); }
            else arow = (size_t)(m0 + r);
            cp16(sA + r * 144 + ch * 16, xb + arow * 1024 + k0 + ch * 4);
            int kr = idx >> 5, nc = idx & 31;
            const float* bp = (nc < 16)
                ? Bg + (size_t)(k0 + kr) * ldb + c0 + nc * 4
                : Bu + (size_t)(k0 + kr) * ldb + c0 + (nc - 16) * 4;
            cp16(sB + kr * 528 + nc * 16, bp);
        }
    };

    float acc[8][8];
#pragma unroll
    for (int i = 0; i < 8; i++)
#pragma unroll
        for (int j = 0; j < 8; j++) acc[i][j] = 0.f;

    const int nch = 32;   // K = 1024
    load_stage(0, 0); cp_commit();
    load_stage(1, 1); cp_commit();

    for (int c = 0; c < nch; c++) {
        if (c + 2 < nch) cp_wait1(); else cp_wait0();
        __syncthreads();
        const int slot = c & 1;
        const float* Ab = smemf + slot * TS_F;
        const float* Bb = smemf + (2 + slot) * TS_F;
#pragma unroll 1
        for (int kq = 0; kq < 8; kq++) {
            float a_[8][4];
#pragma unroll
            for (int i = 0; i < 8; i++) {
                float4 f = *(const float4*)&Ab[(ty * 8 + i) * 36 + kq * 4];
                a_[i][0] = f.x; a_[i][1] = f.y; a_[i][2] = f.z; a_[i][3] = f.w;
            }
#pragma unroll
            for (int kk = 0; kk < 4; kk++) {
                float4 b0 = *(const float4*)&Bb[(kq * 4 + kk) * 132 + tx * 4];
                float4 b1 = *(const float4*)&Bb[(kq * 4 + kk) * 132 + 64 + tx * 4];
#pragma unroll
                for (int i = 0; i < 8; i++) {
                    float av = a_[i][kk];
                    acc[i][0] = fmaf(av, b0.x, acc[i][0]);
                    acc[i][1] = fmaf(av, b0.y, acc[i][1]);
                    acc[i][2] = fmaf(av, b0.z, acc[i][2]);
                    acc[i][3] = fmaf(av, b0.w, acc[i][3]);
                    acc[i][4] = fmaf(av, b1.x, acc[i][4]);
                    acc[i][5] = fmaf(av, b1.y, acc[i][5]);
                    acc[i][6] = fmaf(av, b1.z, acc[i][6]);
                    acc[i][7] = fmaf(av, b1.w, acc[i][7]);
                }
            }
        }
        __syncthreads();
        if (c + 2 < nch) { load_stage(c + 2, slot); cp_commit(); }
    }

    // epilogue: silu(g)*u, 64 act cols per tile
#pragma unroll
    for (int i = 0; i < 8; i++) {
        int lr = ty * 8 + i;
        float* crow;
        if (gather) {
            int jj = rows_s[lr];
            if (jj < 0) continue;
            crow = Cp + (size_t)jj * ldc;
        } else {
            crow = Cp + (size_t)(m0 + lr) * ldc;
        }
        float4 v;
        float g0 = acc[i][0], g1 = acc[i][1], g2 = acc[i][2], g3 = acc[i][3];
        v.x = g0 / (1.f + __expf(-g0)) * acc[i][4];
        v.y = g1 / (1.f + __expf(-g1)) * acc[i][5];
        v.z = g2 / (1.f + __expf(-g2)) * acc[i][6];
        v.w = g3 / (1.f + __expf(-g3)) * acc[i][7];
        *(float4*)&crow[c0 + tx * 4] = v;
    }
}

// ---------------- merged MoE DOWN (as round 15) ----------------
__global__ __launch_bounds__(256, 2)
void moe_down(const float* __restrict__ act, const float* __restrict__ ed,
              float* __restrict__ edb,
              const float* __restrict__ act2, const float* __restrict__ sd,
              float* __restrict__ sdp,
              const int* __restrict__ cnt, const int* __restrict__ list) {
    extern __shared__ __align__(16) float smemf[];
    __shared__ int rows_s[128];
    const int tid = threadIdx.x;
    const int tx = tid & 15, ty = tid >> 4;
    const int n0 = blockIdx.x * 128;
    const int m0 = blockIdx.y * 128;
    const int z = blockIdx.z;
    const bool gather = (z < 32);
    const int zz = z - 32;

    const float* A; const float* Bp; float* C;
    int lda, kb;
    if (gather) {
        int me = cnt[z];
        if (m0 >= me) return;
        if (tid < 128) rows_s[tid] = (m0 + tid < me) ? list[z * T + m0 + tid] : -1;
        __syncthreads();
        A = act; lda = 512; kb = 0;
        Bp = ed + (size_t)z * (512 * 1024);
        C = edb;
    } else {
        A = act2; lda = 1024; kb = zz * 512;
        Bp = sd;
        C = sdp + (size_t)zz * ((size_t)T * H);
    }
    const uint32_t sb = (uint32_t)__cvta_generic_to_shared(smemf);

    auto load_stage = [&](int cc, int slot) {
        const int k0 = kb + cc * 32;
        const uint32_t sA = sb + slot * (TS_F * 4);
        const uint32_t sB = sb + (2 * TS_F + slot * TS_F) * 4;
#pragma unroll
        for (int it = 0; it < 4; it++) {
            int idx = tid + it * 256;
            int r = idx >> 3, ch = idx & 7;
            size_t arow;
            if (gather) { int j = rows_s[r]; arow = (j < 0) ? 0 : (size_t)j; }
            else arow = (size_t)(m0 + r);
            cp16(sA + r * 144 + ch * 16, A + arow * lda + (k0 - kb) + (gather ? 0 : kb) + ch * 4);
            int kr = idx >> 5, nc = idx & 31;
            cp16(sB + kr * 528 + nc * 16, Bp + (size_t)(k0 + kr) * 1024 + n0 + nc * 4);
        }
    };

    float acc[8][8];
#pragma unroll
    for (int i = 0; i < 8; i++)
#pragma unroll
        for (int j = 0; j < 8; j++) acc[i][j] = 0.f;

    const int nch = 16;   // K = 512
    load_stage(0, 0); cp_commit();
    load_stage(1, 1); cp_commit();

    for (int c = 0; c < nch; c++) {
        if (c + 2 < nch) cp_wait1(); else cp_wait0();
        __syncthreads();
        const int slot = c & 1;
        const float* Ab = smemf + slot * TS_F;
        const float* Bb = smemf + (2 + slot) * TS_F;
#pragma unroll 1
        for (int kq = 0; kq < 8; kq++) {
            float a_[8][4];
#pragma unroll
            for (int i = 0; i < 8; i++) {
                float4 f = *(const float4*)&Ab[(ty * 8 + i) * 36 + kq * 4];
                a_[i][0] = f.x; a_[i][1] = f.y; a_[i][2] = f.z; a_[i][3] = f.w;
            }
#pragma unroll
            for (int kk = 0; kk < 4; kk++) {
                float4 b0 = *(const float4*)&Bb[(kq * 4 + kk) * 132 + tx * 4];
                float4 b1 = *(const float4*)&Bb[(kq * 4 + kk) * 132 + 64 + tx * 4];
#pragma unroll
                for (int i = 0; i < 8; i++) {
                    float av = a_[i][kk];
                    acc[i][0] = fmaf(av, b0.x, acc[i][0]);
                    acc[i][1] = fmaf(av, b0.y, acc[i][1]);
                    acc[i][2] = fmaf(av, b0.z, acc[i][2]);
                    acc[i][3] = fmaf(av, b0.w, acc[i][3]);
                    acc[i][4] = fmaf(av, b1.x, acc[i][4]);
                    acc[i][5] = fmaf(av, b1.y, acc[i][5]);
                    acc[i][6] = fmaf(av, b1.z, acc[i][6]);
                    acc[i][7] = fmaf(av, b1.w, acc[i][7]);
                }
            }
        }
        __syncthreads();
        if (c + 2 < nch) { load_stage(c + 2, slot); cp_commit(); }
    }

#pragma unroll
    for (int i = 0; i < 8; i++) {
        int lr = ty * 8 + i;
        float* crow;
        if (gather) {
            int jj = rows_s[lr];
            if (jj < 0) continue;
            crow = C + (size_t)jj * 1024;
        } else {
            crow = C + (size_t)(m0 + lr) * 1024;
        }
#pragma unroll
        for (int jh = 0; jh < 2; jh++)
            *(float4*)&crow[n0 + jh * 64 + tx * 4] =
                make_float4(acc[i][jh*4+0], acc[i][jh*4+1], acc[i][jh*4+2], acc[i][jh*4+3]);
    }
}

// ---------------- split-KV flash attention ----------------
#define ATT_SMEM ((4224 + 8448 + 8448 + 2176) * 4)

__global__ __launch_bounds__(256, 2)
void attn_kernel(const float* __restrict__ qkv, float* __restrict__ po,
                 float* __restrict__ pm, float* __restrict__ pl) {
    extern __shared__ __align__(16) float sm[];
    float* Qs = sm;
    float* Ks = sm + 4224;
    float* Vs = sm + 12672;
    float* Ps = sm + 21120;
    const int h = blockIdx.x;
    const int y = blockIdx.y;
    const int qt = (y < 32) ? (31 - y) : (63 - y);
    const int c  = (y < 32) ? 0 : 1;
    const int ntile = (qt >> 1) + 1;
    const int kt0 = c ? 8 : 0;
    const int kt1 = c ? ntile : min(8, ntile);
    const int kvh = h >> 1;
    const int tid = threadIdx.x;
    const int tx = tid & 15, ty = tid >> 4;
    const uint32_t sb = (uint32_t)__cvta_generic_to_shared(sm);

#pragma unroll
    for (int it = 0; it < 4; it++) {
        int idx = tid + it * 256;
        int r = idx >> 5, cc = idx & 31;
        cp16(sb + (r * 132 + cc * 4) * 4,
             qkv + (size_t)(qt * 32 + r) * 2048 + h * 128 + cc * 4);
    }
    cp_commit();

    float m_[2] = {-1e30f, -1e30f}, l_[2] = {0.f, 0.f};
    float o_[2][8];
#pragma unroll
    for (int i = 0; i < 2; i++)
#pragma unroll
        for (int j = 0; j < 8; j++) o_[i][j] = 0.f;

    const float scale = 0.088388347648318447f;
    const int qg0 = qt * 32 + ty * 2;

    for (int kt = kt0; kt < kt1; kt++) {
        __syncthreads();
#pragma unroll
        for (int it = 0; it < 8; it++) {
            int idx = tid + it * 256;
            int r = idx >> 5, cc = idx & 31;
            cp16(sb + (4224 + r * 132 + cc * 4) * 4,
                 qkv + (size_t)(kt * 64 + r) * 2048 + 1024 + kvh * 128 + cc * 4);
        }
#pragma unroll
        for (int it = 0; it < 8; it++) {
            int idx = tid + it * 256;
            int r = idx >> 5, cc = idx & 31;
            cp16(sb + (12672 + r * 132 + cc * 4) * 4,
                 qkv + (size_t)(kt * 64 + r) * 2048 + 1536 + kvh * 128 + cc * 4);
        }
        cp_commit();
        cp_wait0();
        __syncthreads();

        float s[2][4];
#pragma unroll
        for (int i = 0; i < 2; i++)
#pragma unroll
            for (int j = 0; j < 4; j++) s[i][j] = 0.f;
#pragma unroll 8
        for (int d4 = 0; d4 < 32; d4++) {
            float4 a0 = *(const float4*)&Qs[(ty * 2 + 0) * 132 + d4 * 4];
            float4 a1 = *(const float4*)&Qs[(ty * 2 + 1) * 132 + d4 * 4];
#pragma unroll
            for (int j = 0; j < 4; j++) {
                float4 b = *(const float4*)&Ks[(j * 16 + tx) * 132 + d4 * 4];
                s[0][j] = fmaf(a0.x, b.x, fmaf(a0.y, b.y, fmaf(a0.z, b.z, fmaf(a0.w, b.w, s[0][j]))));
                s[1][j] = fmaf(a1.x, b.x, fmaf(a1.y, b.y, fmaf(a1.z, b.z, fmaf(a1.w, b.w, s[1][j]))));
            }
        }
#pragma unroll
        for (int i = 0; i < 2; i++)
#pragma unroll
            for (int j = 0; j < 4; j++) {
                int kg = kt * 64 + j * 16 + tx;
                s[i][j] = (kg <= qg0 + i) ? s[i][j] * scale : -1e30f;
            }
#pragma unroll
        for (int i = 0; i < 2; i++) {
            float mt = fmaxf(fmaxf(s[i][0], s[i][1]), fmaxf(s[i][2], s[i][3]));
            mt = fmaxf(mt, __shfl_xor_sync(0xffffffffu, mt, 8));
            mt = fmaxf(mt, __shfl_xor_sync(0xffffffffu, mt, 4));
            mt = fmaxf(mt, __shfl_xor_sync(0xffffffffu, mt, 2));
            mt = fmaxf(mt, __shfl_xor_sync(0xffffffffu, mt, 1));
            float mn = fmaxf(m_[i], mt);
            float corr = __expf(m_[i] - mn);
            float p0 = __expf(s[i][0] - mn), p1 = __expf(s[i][1] - mn);
            float p2 = __expf(s[i][2] - mn), p3 = __expf(s[i][3] - mn);
            float rs = p0 + p1 + p2 + p3;
            rs += __shfl_xor_sync(0xffffffffu, rs, 8);
            rs += __shfl_xor_sync(0xffffffffu, rs, 4);
            rs += __shfl_xor_sync(0xffffffffu, rs, 2);
            rs += __shfl_xor_sync(0xffffffffu, rs, 1);
            l_[i] = l_[i] * corr + rs;
            m_[i] = mn;
#pragma unroll
            for (int jj = 0; jj < 8; jj++) o_[i][jj] *= corr;
            int prow = (ty * 2 + i) * 68;
            Ps[prow + tx]      = p0;
            Ps[prow + 16 + tx] = p1;
            Ps[prow + 32 + tx] = p2;
            Ps[prow + 48 + tx] = p3;
        }
        __syncthreads();
#pragma unroll 4
        for (int k = 0; k < 64; k++) {
            float p0 = Ps[(ty * 2 + 0) * 68 + k];
            float p1 = Ps[(ty * 2 + 1) * 68 + k];
            float4 v0 = *(const float4*)&Vs[k * 132 + tx * 4];
            float4 v1 = *(const float4*)&Vs[k * 132 + 64 + tx * 4];
            o_[0][0] = fmaf(p0, v0.x, o_[0][0]); o_[0][1] = fmaf(p0, v0.y, o_[0][1]);
            o_[0][2] = fmaf(p0, v0.z, o_[0][2]); o_[0][3] = fmaf(p0, v0.w, o_[0][3]);
            o_[0][4] = fmaf(p0, v1.x, o_[0][4]); o_[0][5] = fmaf(p0, v1.y, o_[0][5]);
            o_[0][6] = fmaf(p0, v1.z, o_[0][6]); o_[0][7] = fmaf(p0, v1.w, o_[0][7]);
            o_[1][0] = fmaf(p1, v0.x, o_[1][0]); o_[1][1] = fmaf(p1, v0.y, o_[1][1]);
            o_[1][2] = fmaf(p1, v0.z, o_[1][2]); o_[1][3] = fmaf(p1, v0.w, o_[1][3]);
            o_[1][4] = fmaf(p1, v1.x, o_[1][4]); o_[1][5] = fmaf(p1, v1.y, o_[1][5]);
            o_[1][6] = fmaf(p1, v1.z, o_[1][6]); o_[1][7] = fmaf(p1, v1.w, o_[1][7]);
        }
    }
#pragma unroll
    for (int i = 0; i < 2; i++) {
        int row = qt * 32 + ty * 2 + i;
        size_t base = (size_t)c * ((size_t)T * H) + (size_t)row * H + h * 128;
        *(float4*)&po[base + tx * 4] =
            make_float4(o_[i][0], o_[i][1], o_[i][2], o_[i][3]);
        *(float4*)&po[base + 64 + tx * 4] =
            make_float4(o_[i][4], o_[i][5], o_[i][6], o_[i][7]);
        if (tx == 0) {
            pm[c * (T * NH) + row * NH + h] = m_[i];
            pl[c * (T * NH) + row * NH + h] = l_[i];
        }
    }
}

__global__ void attn_combine(const float* __restrict__ po, const float* __restrict__ pm,
                             const float* __restrict__ pl, float* __restrict__ out) {
    int idx = blockIdx.x * blockDim.x + threadIdx.x;
    if (idx >= T * H) return;
    int q = idx >> 10;
    int h = (idx & 1023) >> 7;
    int qt = q >> 5;
    float m0 = pm[q * NH + h], l0 = pl[q * NH + h];
    float o0 = po[idx];
    if (qt >= 16) {
        float m1 = pm[T * NH + q * NH + h], l1 = pl[T * NH + q * NH + h];
        float o1 = po[(size_t)T * H + idx];
        float mm = fmaxf(m0, m1);
        float e0 = __expf(m0 - mm), e1 = __expf(m1 - mm);
        out[idx] = (o0 * e0 + o1 * e1) / (l0 * e0 + l1 * e1);
    } else {
        out[idx] = o0 / l0;
    }
}

// ---------------- elementwise / norms ----------------
__global__ void rmsnorm_kernel(const float* __restrict__ x, const float* __restrict__ w,
                               float* __restrict__ out) {
    int t = blockIdx.x;
    const float* xr = x + (size_t)t * H;
    float s = 0.f;
    for (int i = threadIdx.x; i < H; i += blockDim.x) { float v = xr[i]; s += v * v; }
    __shared__ float red[32];
    for (int o = 16; o; o >>= 1) s += __shfl_xor_sync(0xffffffffu, s, o);
    if ((threadIdx.x & 31) == 0) red[threadIdx.x >> 5] = s;
    __syncthreads();
    if (threadIdx.x < 32) {
        float v = (threadIdx.x < (blockDim.x >> 5)) ? red[threadIdx.x] : 0.f;
        for (int o = 16; o; o >>= 1) v += __shfl_xor_sync(0xffffffffu, v, o);
        if (threadIdx.x == 0) red[0] = v;
    }
    __syncthreads();
    float inv = rsqrtf(red[0] * (1.f / H) + 1e-6f);
    for (int i = threadIdx.x; i < H; i += blockDim.x)
        out[(size_t)t * H + i] = xr[i] * inv * w[i];
}

__global__ void add_rmsnorm_kernel(const float* __restrict__ a, const float* __restrict__ b,
                                   const float* __restrict__ c, const float* __restrict__ w,
                                   float* __restrict__ h2, float* __restrict__ xb) {
    int t = blockIdx.x;
    size_t base = (size_t)t * H;
    float s = 0.f;
    for (int i = threadIdx.x; i < H; i += blockDim.x) {
        float v = a[base + i] + b[base + i] + c[base + i];
        h2[base + i] = v;
        s += v * v;
    }
    __shared__ float red[32];
    for (int o = 16; o; o >>= 1) s += __shfl_xor_sync(0xffffffffu, s, o);
    if ((threadIdx.x & 31) == 0) red[threadIdx.x >> 5] = s;
    __syncthreads();
    if (threadIdx.x < 32) {
        float v = (threadIdx.x < (blockDim.x >> 5)) ? red[threadIdx.x] : 0.f;
        for (int o = 16; o; o >>= 1) v += __shfl_xor_sync(0xffffffffu, v, o);
        if (threadIdx.x == 0) red[0] = v;
    }
    __syncthreads();
    float inv = rsqrtf(red[0] * (1.f / H) + 1e-6f);
    for (int i = threadIdx.x; i < H; i += blockDim.x)
        xb[base + i] = h2[base + i] * inv * w[i];
}

__global__ void zero_cnt_kernel(int* cnt) { if (threadIdx.x < NE) cnt[threadIdx.x] = 0; }

// ---------------- router ----------------
__global__ void router_gemm(const float* __restrict__ xb, const float* __restrict__ rw,
                            float* __restrict__ logits) {
    __shared__ float xr[H];
    int t = blockIdx.x;
    for (int i = threadIdx.x; i < H; i += 128) xr[i] = xb[(size_t)t * H + i];
    __syncthreads();
    int w = threadIdx.x >> 5, lane = threadIdx.x & 31;
    for (int e8 = 0; e8 < 8; e8++) {
        int e = w * 8 + e8;
        const float* wr = rw + (size_t)e * H;
        float s = 0.f;
        for (int k = lane; k < H; k += 32) s += xr[k] * wr[k];
        for (int o = 16; o; o >>= 1) s += __shfl_xor_sync(0xffffffffu, s, o);
        if (lane == 0) logits[t * NE + e] = s;
    }
}

__global__ void router_kernel(const float* __restrict__ logits, const float* __restrict__ bias,
                              float* __restrict__ topkw, int* __restrict__ cnt,
                              int* __restrict__ list) {
    int t = blockIdx.x * blockDim.x + threadIdx.x;
    if (t >= T) return;
    float sc[NE], sfc[NE];
#pragma unroll
    for (int e = 0; e < NE; e++) {
        float l = logits[t * NE + e];
        float s = 1.f / (1.f + __expf(-l));
        sc[e] = s; sfc[e] = s + bias[e];
    }
    float gs[8];
#pragma unroll
    for (int g = 0; g < 8; g++) {
        float v[4] = {sfc[g*4+0], sfc[g*4+1], sfc[g*4+2], sfc[g*4+3]};
        float sum = v[0] + v[1] + v[2] + v[3];
        int mi = 0;
        for (int i = 1; i < 4; i++) if (v[i] < v[mi]) mi = i;
        float m2 = 1e30f;
        for (int i = 0; i < 4; i++) if (i != mi && v[i] < m2) m2 = v[i];
        gs[g] = sum - v[mi] - m2;
    }
    bool gsel[8] = {};
    for (int r = 0; r < 4; r++) {
        float best = -1e30f; int bi = 0;
        for (int g = 0; g < 8; g++) if (!gsel[g] && gs[g] > best) { best = gs[g]; bi = g; }
        gsel[bi] = true;
    }
    float masked[NE];
#pragma unroll
    for (int e = 0; e < NE; e++) masked[e] = gsel[e >> 2] ? sfc[e] : 0.f;
    int idxs[4]; float ws[4]; float wsum = 0.f;
    for (int r = 0; r < 4; r++) {
        float best = -1e30f; int bi = 0;
        for (int e = 0; e < NE; e++) if (masked[e] > best) { best = masked[e]; bi = e; }
        masked[bi] = -1e30f;
        idxs[r] = bi; ws[r] = sc[bi]; wsum += ws[r];
    }
    float inv = 2.5f / (wsum + 1e-20f);
    for (int r = 0; r < 4; r++) {
        topkw[t * 4 + r] = ws[r] * inv;
        int pos = atomicAdd(&cnt[idxs[r]], 1);
        list[idxs[r] * T + pos] = t * 4 + r;
    }
}

// final: out = h2 + shared_down(p0+p1) + sum_k tw*ed
__global__ void final_kernel(const float* __restrict__ h2, const float* __restrict__ p0,
                             const float* __restrict__ p1, const float* __restrict__ ed,
                             const float* __restrict__ tw, float* __restrict__ out) {
    int idx = blockIdx.x * blockDim.x + threadIdx.x;
    if (idx >= T * H) return;
    int t = idx >> 10;
    int hh = idx & 1023;
    float r = h2[idx] + p0[idx] + p1[idx];
#pragma unroll
    for (int kk = 0; kk < 4; kk++)
        r += tw[t * 4 + kk] * ed[(size_t)(t * 4 + kk) * H + hh];
    out[idx] = r;
}

// ---------------- host ----------------
extern "C" void kernel_launch(void* const* d_in, const int* in_sizes, int n_in,
                              void* d_out, int out_size) {
    (void)in_sizes; (void)n_in; (void)out_size;
    const float* hidden   = (const float*)d_in[0];
    const int*   pos      = (const int*)d_in[1];
    const float* ln1_w    = (const float*)d_in[2];
    const float* ln2_w    = (const float*)d_in[3];
    const float* q_w      = (const float*)d_in[4];
    const float* k_w      = (const float*)d_in[5];
    const float* v_w      = (const float*)d_in[6];
    const float* o_w      = (const float*)d_in[7];
    const float* router_w = (const float*)d_in[8];
    const float* r_bias   = (const float*)d_in[9];
    const float* eg_w     = (const float*)d_in[10];
    const float* eu_w     = (const float*)d_in[11];
    const float* ed_w     = (const float*)d_in[12];
    const float* sg_w     = (const float*)d_in[13];
    const float* su_w     = (const float*)d_in[14];
    const float* sd_w     = (const float*)d_in[15];
    float* out = (float*)d_out;

#define GSYM(p, s) cudaGetSymbolAddress((void**)&p, s)
    float *h1, *qkv, *at, *h2, *xb, *logits, *topkw, *part, *act, *edb, *act2, *sdp, *pm, *pl;
    int *cnt, *list;
    GSYM(h1,g_h1); GSYM(qkv,g_qkv); GSYM(at,g_at); GSYM(h2,g_h2); GSYM(xb,g_xb);
    GSYM(logits,g_logits); GSYM(topkw,g_topkw); GSYM(cnt,g_cnt); GSYM(list,g_list);
    GSYM(part,g_part); GSYM(act,g_act); GSYM(edb,g_edb);
    GSYM(act2,g_act2); GSYM(sdp,g_sdp); GSYM(pm,g_pm); GSYM(pl,g_pl);
#undef GSYM
    float* part0 = part;
    float* part1 = part + (size_t)T * H;
    float* po = act;                         // attn partial O (pre-MoE only)
    float* sdp0 = sdp;
    float* sdp1 = sdp + (size_t)T * H;

    cudaFuncSetAttribute(fgemm_nt<false,true>, cudaFuncAttributeMaxDynamicSharedMemorySize, GEMM_SMEM);
    cudaFuncSetAttribute(fgemm_nt<true,false>, cudaFuncAttributeMaxDynamicSharedMemorySize, GEMM_SMEM);
    cudaFuncSetAttribute(moe_up,   cudaFuncAttributeMaxDynamicSharedMemorySize, GEMM_SMEM);
    cudaFuncSetAttribute(moe_down, cudaFuncAttributeMaxDynamicSharedMemorySize, GEMM_SMEM);
    cudaFuncSetAttribute(attn_kernel, cudaFuncAttributeMaxDynamicSharedMemorySize, ATT_SMEM);
    cudaFuncSetAttribute(attn_kernel, cudaFuncAttributePreferredSharedMemoryCarveout, 100);

    // ---- attention branch (attn at my launch #4 for ncu) ----
    rmsnorm_kernel<<<T, 256>>>(hidden, ln1_w, h1);                          // 1
    {   // 2: fused QKV GEMM (NT) + RoPE epilogue
        Bseg b = {{q_w, q_w, k_w, v_w}, {0, 0, 1024, 1536}};
        fgemm_nt<false,true><<<dim3(16, 8), 256, GEMM_SMEM>>>(
            h1, 1024, b, 1024, qkv, 2048, 0, 1024, pos);
    }
    zero_cnt_kernel<<<1, 32>>>(cnt);                                        // 3 (filler)
    attn_kernel<<<dim3(NH, 48), 256, ATT_SMEM>>>(qkv, po, pm, pl);          // 4 <-- PROFILED
    attn_combine<<<(T * H + 255) / 256, 256>>>(po, pm, pl, at);             // 5
    {   // O projection (NT), split-K=2
        Bseg b = {{o_w, o_w, o_w, o_w}, {0, 0, 0, 0}};
        fgemm_nt<true,false><<<dim3(8, 8, 2), 256, GEMM_SMEM>>>(
            at, 1024, b, 1024, part0, 1024, (size_t)T * H, 512, nullptr);
    }
    add_rmsnorm_kernel<<<T, 256>>>(hidden, part0, part1, ln2_w, h2, xb);

    // ---- MoE (merged routed + shared) ----
    router_gemm<<<T, 128>>>(xb, router_w, logits);
    router_kernel<<<(T + 255) / 256, 256>>>(logits, r_bias, topkw, cnt, list);

    // merged UP with fused SiLU: z<32 experts (x<8), z=32 shared (x<16)
    moe_up<<<dim3(16, 8, 33), 256, GEMM_SMEM>>>(
        xb, eg_w, eu_w, sg_w, su_w, act, act2, cnt, list);

    // merged DOWN: z<32 experts, z=32/33 shared sd split-K halves
    moe_down<<<dim3(8, 8, 34), 256, GEMM_SMEM>>>(
        act, ed_w, edb, act2, sd_w, sdp0, cnt, list);

    final_kernel<<<(T * H + 255) / 256, 256>>>(h2, sdp0, sdp1, edb, topkw, out);
}